// round 2
// baseline (speedup 1.0000x reference)
#include <cuda_runtime.h>
#include <math.h>

// Problem constants
#define B_SZ    16
#define N_SEQ   1024
#define H_HEADS 2
#define D_HEAD  128
#define A_DIM   256
#define FFN_DIM 1024
#define DEPTH   3
#define ROWS    (B_SZ * N_SEQ)   // 16384
#define LN_EPS  1e-5f

// GEMM tile config: 128x128x16, 256 threads, 8x8 micro-tile
#define GBM 128
#define GBN 128
#define GBK 16

// Flash attention tiles
#define QT 64
#define KT 64
#define QPITCH 68            // padded pitch for transposed smem tiles
#define FLASH_SMEM_BYTES ((2 * 128 * QPITCH + KT * QPITCH) * 4)  // 87040

// ---------------- scratch (static device globals; no allocation) ------------
__device__ float g_step[ROWS * A_DIM];
__device__ float g_q   [ROWS * A_DIM];
__device__ float g_k   [ROWS * A_DIM];
__device__ float g_v   [ROWS * A_DIM];
__device__ float g_attn[ROWS * A_DIM];
__device__ float g_roll[ROWS * A_DIM];
__device__ float g_h   [ROWS * FFN_DIM];

// ---------------- block reductions (256 threads) ----------------------------
__device__ __forceinline__ float blockReduceSum256(float v) {
    __shared__ float s[8];
    __syncthreads();
#pragma unroll
    for (int o = 16; o; o >>= 1) v += __shfl_xor_sync(0xffffffffu, v, o);
    if ((threadIdx.x & 31) == 0) s[threadIdx.x >> 5] = v;
    __syncthreads();
    float r = s[0];
#pragma unroll
    for (int i = 1; i < 8; i++) r += s[i];
    return r;
}

// ---------------- 128x128x16 GEMM body, 8x8 per thread ----------------------
__device__ __forceinline__ void gemm128_body(
    const float* __restrict__ A, const float* __restrict__ B,
    const float* __restrict__ bias, float* __restrict__ C,
    int K, int lda, int ldb, int ldc, int relu, int m0, int n0)
{
    __shared__ float As[GBK][GBM];
    __shared__ float Bs[GBK][GBN];
    const int tid = threadIdx.x;
    const int tx = tid & 15;
    const int ty = tid >> 4;

    float acc[8][8] = {};
    for (int k0 = 0; k0 < K; k0 += GBK) {
#pragma unroll
        for (int r = 0; r < 2; r++) {
            int idx = tid + r * 256;
            int row = idx >> 2;          // 0..127
            int cq  = (idx & 3) << 2;    // 0,4,8,12
            float4 av = *(const float4*)(A + (size_t)(m0 + row) * lda + k0 + cq);
            As[cq + 0][row] = av.x;
            As[cq + 1][row] = av.y;
            As[cq + 2][row] = av.z;
            As[cq + 3][row] = av.w;
        }
#pragma unroll
        for (int r = 0; r < 2; r++) {
            int idx = tid + r * 256;
            int row = idx >> 5;          // 0..15
            int col = (idx & 31) << 2;   // 0..124
            *(float4*)&Bs[row][col] =
                *(const float4*)(B + (size_t)(k0 + row) * ldb + n0 + col);
        }
        __syncthreads();
#pragma unroll
        for (int kk = 0; kk < GBK; kk++) {
            float4 a0 = *(const float4*)&As[kk][ty * 8];
            float4 a1 = *(const float4*)&As[kk][ty * 8 + 4];
            float4 b0 = *(const float4*)&Bs[kk][tx * 8];
            float4 b1 = *(const float4*)&Bs[kk][tx * 8 + 4];
            float ar[8] = {a0.x, a0.y, a0.z, a0.w, a1.x, a1.y, a1.z, a1.w};
            float br[8] = {b0.x, b0.y, b0.z, b0.w, b1.x, b1.y, b1.z, b1.w};
#pragma unroll
            for (int i = 0; i < 8; i++)
#pragma unroll
                for (int j = 0; j < 8; j++)
                    acc[i][j] = fmaf(ar[i], br[j], acc[i][j]);
        }
        __syncthreads();
    }

    float bb[8] = {};
    if (bias) {
        float4 c0 = *(const float4*)(bias + n0 + tx * 8);
        float4 c1 = *(const float4*)(bias + n0 + tx * 8 + 4);
        bb[0] = c0.x; bb[1] = c0.y; bb[2] = c0.z; bb[3] = c0.w;
        bb[4] = c1.x; bb[5] = c1.y; bb[6] = c1.z; bb[7] = c1.w;
    }
#pragma unroll
    for (int i = 0; i < 8; i++) {
        int m = m0 + ty * 8 + i;
        float o[8];
#pragma unroll
        for (int j = 0; j < 8; j++) {
            o[j] = acc[i][j] + bb[j];
            if (relu) o[j] = fmaxf(o[j], 0.f);
        }
        *(float4*)(C + (size_t)m * ldc + n0 + tx * 8)     = make_float4(o[0], o[1], o[2], o[3]);
        *(float4*)(C + (size_t)m * ldc + n0 + tx * 8 + 4) = make_float4(o[4], o[5], o[6], o[7]);
    }
}

__global__ void __launch_bounds__(256) k_gemm128(
    const float* __restrict__ A, const float* __restrict__ B,
    const float* __restrict__ bias, float* __restrict__ C,
    int K, int lda, int ldb, int ldc, int relu)
{
    gemm128_body(A, B, bias, C, K, lda, ldb, ldc, relu,
                 blockIdx.y * GBM, blockIdx.x * GBN);
}

// Fused QKV: blockIdx.z selects projection; A tile read stays hot in L2.
__global__ void __launch_bounds__(256) k_qkv(
    const float* __restrict__ A,
    const float* __restrict__ W0, const float* __restrict__ W1, const float* __restrict__ W2,
    const float* __restrict__ c0, const float* __restrict__ c1, const float* __restrict__ c2,
    float* __restrict__ O0, float* __restrict__ O1, float* __restrict__ O2)
{
    const float* W; const float* bb; float* O;
    if (blockIdx.z == 0)      { W = W0; bb = c0; O = O0; }
    else if (blockIdx.z == 1) { W = W1; bb = c1; O = O1; }
    else                      { W = W2; bb = c2; O = O2; }
    gemm128_body(A, W, bb, O, A_DIM, A_DIM, A_DIM, A_DIM, 0,
                 blockIdx.y * GBM, blockIdx.x * GBN);
}

// ---------------- fused flash attention -------------------------------------
// One block: (b,h) = blockIdx.y, q-tile of 64 rows = blockIdx.x.
// Online softmax; Q/K transposed in smem (d-major) for conflict-free compute.
__global__ void __launch_bounds__(256, 2) k_flash(
    const float* __restrict__ Q, const float* __restrict__ K,
    const float* __restrict__ V, float* __restrict__ Out, float alpha)
{
    const int bh = blockIdx.y;
    const int b  = bh >> 1, h = bh & 1;
    const int q0 = blockIdx.x * QT;
    const int tid = threadIdx.x;
    const int tx = tid & 15;
    const int ty = tid >> 4;
    const size_t base = (size_t)b * N_SEQ * A_DIM + (size_t)h * D_HEAD;

    extern __shared__ float sm[];
    float* Qst = sm;                       // [128][QPITCH]  Qst[d][qrow]
    float* Kst = sm + 128 * QPITCH;        // [128][QPITCH]  Kst[d][krow]
    float* Vs  = sm + 128 * QPITCH;        // [64][128] (reuses Kst region)
    float* Pst = sm + 2 * 128 * QPITCH;    // [64][QPITCH]   Pst[key][qrow]

    // Load Q tile transposed
#pragma unroll
    for (int r = 0; r < 8; r++) {
        int idx = tid + r * 256;           // 64 rows x 32 float4
        int row = idx >> 5;
        int d4  = (idx & 31) << 2;
        float4 vq = *(const float4*)(Q + base + (size_t)(q0 + row) * A_DIM + d4);
        Qst[(d4 + 0) * QPITCH + row] = vq.x;
        Qst[(d4 + 1) * QPITCH + row] = vq.y;
        Qst[(d4 + 2) * QPITCH + row] = vq.z;
        Qst[(d4 + 3) * QPITCH + row] = vq.w;
    }

    float o[4][8] = {};
    float mrow[4] = {-1e30f, -1e30f, -1e30f, -1e30f};
    float lrow[4] = {0.f, 0.f, 0.f, 0.f};

    for (int t = 0; t < N_SEQ / KT; t++) {
        const int k0 = t * KT;
        __syncthreads();   // prev iter's Vs/Pst consumed; Kst region free
        // Load K tile transposed
#pragma unroll
        for (int r = 0; r < 8; r++) {
            int idx = tid + r * 256;
            int row = idx >> 5;
            int d4  = (idx & 31) << 2;
            float4 vk = *(const float4*)(K + base + (size_t)(k0 + row) * A_DIM + d4);
            Kst[(d4 + 0) * QPITCH + row] = vk.x;
            Kst[(d4 + 1) * QPITCH + row] = vk.y;
            Kst[(d4 + 2) * QPITCH + row] = vk.z;
            Kst[(d4 + 3) * QPITCH + row] = vk.w;
        }
        __syncthreads();

        // S tile: 4x4 per thread over d=128
        float s[4][4] = {};
#pragma unroll 8
        for (int kk = 0; kk < D_HEAD; kk++) {
            float4 a  = *(const float4*)&Qst[kk * QPITCH + ty * 4];
            float4 bv = *(const float4*)&Kst[kk * QPITCH + tx * 4];
            float ar[4] = {a.x, a.y, a.z, a.w};
            float br[4] = {bv.x, bv.y, bv.z, bv.w};
#pragma unroll
            for (int i = 0; i < 4; i++)
#pragma unroll
                for (int j = 0; j < 4; j++)
                    s[i][j] = fmaf(ar[i], br[j], s[i][j]);
        }

        // Online softmax update (rows ty*4+i; reduce across 16 tx lanes)
#pragma unroll
        for (int i = 0; i < 4; i++) {
            float rmax = -1e30f;
#pragma unroll
            for (int j = 0; j < 4; j++) {
                s[i][j] *= alpha;
                rmax = fmaxf(rmax, s[i][j]);
            }
#pragma unroll
            for (int w = 1; w < 16; w <<= 1)
                rmax = fmaxf(rmax, __shfl_xor_sync(0xffffffffu, rmax, w));
            float mnew = fmaxf(mrow[i], rmax);
            float scale = __expf(mrow[i] - mnew);
            mrow[i] = mnew;
            lrow[i] *= scale;
#pragma unroll
            for (int j = 0; j < 8; j++) o[i][j] *= scale;
            float rsum = 0.f;
#pragma unroll
            for (int j = 0; j < 4; j++) {
                float p = __expf(s[i][j] - mnew);
                s[i][j] = p;
                rsum += p;
            }
#pragma unroll
            for (int w = 1; w < 16; w <<= 1)
                rsum += __shfl_xor_sync(0xffffffffu, rsum, w);
            lrow[i] += rsum;
#pragma unroll
            for (int j = 0; j < 4; j++)
                Pst[(tx * 4 + j) * QPITCH + ty * 4 + i] = s[i][j];
        }
        __syncthreads();   // Kst reads + Pst writes complete

        // Load V tile (row-major) into Kst region
#pragma unroll
        for (int r = 0; r < 8; r++) {
            int idx = tid + r * 256;
            int row = idx >> 5;
            int d4  = (idx & 31) << 2;
            *(float4*)&Vs[row * 128 + d4] =
                *(const float4*)(V + base + (size_t)(k0 + row) * A_DIM + d4);
        }
        __syncthreads();

        // O += P @ V   (4 rows x 8 cols per thread over 64 keys)
#pragma unroll 4
        for (int kk = 0; kk < KT; kk++) {
            float4 a  = *(const float4*)&Pst[kk * QPITCH + ty * 4];
            float4 b0 = *(const float4*)&Vs[kk * 128 + tx * 8];
            float4 b1 = *(const float4*)&Vs[kk * 128 + tx * 8 + 4];
            float ar[4] = {a.x, a.y, a.z, a.w};
            float br[8] = {b0.x, b0.y, b0.z, b0.w, b1.x, b1.y, b1.z, b1.w};
#pragma unroll
            for (int i = 0; i < 4; i++)
#pragma unroll
                for (int j = 0; j < 8; j++)
                    o[i][j] = fmaf(ar[i], br[j], o[i][j]);
        }
    }

    // Normalize and store: Out[b, q0+row, h*128 + col]
#pragma unroll
    for (int i = 0; i < 4; i++) {
        float inv = 1.f / lrow[i];
        float w0[4], w1[4];
#pragma unroll
        for (int j = 0; j < 4; j++) { w0[j] = o[i][j] * inv; w1[j] = o[i][j + 4] * inv; }
        float* dst = Out + base + (size_t)(q0 + ty * 4 + i) * A_DIM + tx * 8;
        *(float4*)dst       = make_float4(w0[0], w0[1], w0[2], w0[3]);
        *(float4*)(dst + 4) = make_float4(w1[0], w1[1], w1[2], w1[3]);
    }
}

// ---------------- LayerNorm(residual) ----------------------------------------
// step_out = LN(roll + prev) * g + b ; one block per row, 256 threads
__global__ void k_ln_residual(const float* __restrict__ roll,
                              const float* __restrict__ prev,
                              float* __restrict__ step,
                              const float* __restrict__ g, const float* __restrict__ b)
{
    const size_t row = blockIdx.x;
    const int t = threadIdx.x;
    float x = roll[row * A_DIM + t] + prev[row * A_DIM + t];
    float mu = blockReduceSum256(x) * (1.f / A_DIM);
    float d = x - mu;
    float var = blockReduceSum256(d * d) * (1.f / A_DIM);
    step[row * A_DIM + t] = d * rsqrtf(var + LN_EPS) * g[t] + b[t];
}

// ---------------- pool + final linear ----------------------------------------
__global__ void k_pool_final(const float* __restrict__ E, const float* __restrict__ We,
                             const float* __restrict__ be, float* __restrict__ out)
{
    const int b = blockIdx.x;
    const int t = threadIdx.x;
    __shared__ float pr[A_DIM];
    const float* base = E + (size_t)b * N_SEQ * A_DIM + t;
    float s0 = 0.f, s1 = 0.f, s2 = 0.f, s3 = 0.f;
    for (int n = 0; n < N_SEQ; n += 4) {
        s0 += base[(size_t)(n + 0) * A_DIM];
        s1 += base[(size_t)(n + 1) * A_DIM];
        s2 += base[(size_t)(n + 2) * A_DIM];
        s3 += base[(size_t)(n + 3) * A_DIM];
    }
    pr[t] = (s0 + s1 + s2 + s3) * (1.f / N_SEQ);
    __syncthreads();
    float acc = 0.f;
#pragma unroll 8
    for (int k = 0; k < A_DIM; k++) acc = fmaf(pr[k], We[k * A_DIM + t], acc);
    out[b * A_DIM + t] = fmaxf(acc + be[t], 0.f);
}

// ---------------- launcher ---------------------------------------------------
extern "C" void kernel_launch(void* const* d_in, const int* in_sizes, int n_in,
                              void* d_out, int out_size)
{
    const float* X   = (const float*)d_in[0];
    const float* Wq  = (const float*)d_in[1];
    const float* bq  = (const float*)d_in[2];
    const float* Wk  = (const float*)d_in[3];
    const float* bk  = (const float*)d_in[4];
    const float* Wv  = (const float*)d_in[5];
    const float* bv  = (const float*)d_in[6];
    const float* W1  = (const float*)d_in[7];
    const float* b1  = (const float*)d_in[8];
    const float* W2  = (const float*)d_in[9];
    const float* b2  = (const float*)d_in[10];
    const float* lng = (const float*)d_in[11];
    const float* lnb = (const float*)d_in[12];
    const float* Wc  = (const float*)d_in[13];
    const float* bc  = (const float*)d_in[14];
    const float* We  = (const float*)d_in[15];
    const float* be  = (const float*)d_in[16];
    float* out = (float*)d_out;

    static float *step = nullptr, *q, *k, *v, *attn, *roll, *hbuf;
    if (!step) {
        cudaGetSymbolAddress((void**)&step, g_step);
        cudaGetSymbolAddress((void**)&q,    g_q);
        cudaGetSymbolAddress((void**)&k,    g_k);
        cudaGetSymbolAddress((void**)&v,    g_v);
        cudaGetSymbolAddress((void**)&attn, g_attn);
        cudaGetSymbolAddress((void**)&roll, g_roll);
        cudaGetSymbolAddress((void**)&hbuf, g_h);
        cudaFuncSetAttribute(k_flash, cudaFuncAttributeMaxDynamicSharedMemorySize,
                             FLASH_SMEM_BYTES);
    }

    const dim3 blk(256);
    const dim3 gQKV(A_DIM / GBN,   ROWS / GBM, 3);   // (2, 128, 3)
    const dim3 gA  (A_DIM / GBN,   ROWS / GBM);      // (2, 128)
    const dim3 gF1 (FFN_DIM / GBN, ROWS / GBM);      // (8, 128)
    const dim3 gFl (N_SEQ / QT, B_SZ * H_HEADS);     // (16, 32)
    const float inv_sqrt_d = 0.08838834764831845f;   // 1/sqrt(128)

    for (int i = 0; i < DEPTH; i++) {
        const float* prev = (i == 0) ? X : step;
        const size_t wo = (size_t)i * A_DIM * A_DIM;
        k_qkv<<<gQKV, blk>>>(prev,
                             Wq + wo, Wk + wo, Wv + wo,
                             bq + i * A_DIM, bk + i * A_DIM, bv + i * A_DIM,
                             q, k, v);
        k_flash<<<gFl, blk, FLASH_SMEM_BYTES>>>(q, k, v, attn, inv_sqrt_d);
        k_gemm128<<<gF1, blk>>>(attn, W1 + (size_t)i * A_DIM * FFN_DIM,
                                b1 + i * FFN_DIM, hbuf,
                                A_DIM, A_DIM, FFN_DIM, FFN_DIM, 1);
        k_gemm128<<<gA, blk>>>(hbuf, W2 + (size_t)i * FFN_DIM * A_DIM,
                               b2 + i * A_DIM, roll,
                               FFN_DIM, FFN_DIM, A_DIM, A_DIM, 1);
        k_ln_residual<<<ROWS, blk>>>(roll, prev, step, lng, lnb);
    }

    // Conv1d(k=1) + ReLU -> entity encodings (reuse attn buffer)
    k_gemm128<<<gA, blk>>>(step, Wc, bc, attn, A_DIM, A_DIM, A_DIM, A_DIM, 1);
    // mean pool + final linear + ReLU
    k_pool_final<<<B_SZ, blk>>>(attn, We, be, out);
}

// round 5
// speedup vs baseline: 3.4531x; 3.4531x over previous
#include <cuda_runtime.h>
#include <math.h>

// Problem constants
#define B_SZ    16
#define N_SEQ   1024
#define H_HEADS 2
#define D_HEAD  128
#define A_DIM   256
#define FFN_DIM 1024
#define DEPTH   3
#define ROWS    (B_SZ * N_SEQ)   // 16384
#define LN_EPS  1e-5f

// ---------------- scratch (static device globals; no allocation) ------------
__device__ float g_step[ROWS * A_DIM];
__device__ float g_q   [ROWS * A_DIM];
__device__ float g_k   [ROWS * A_DIM];
__device__ float g_v   [ROWS * A_DIM];
__device__ float g_attn[ROWS * A_DIM];
__device__ float g_roll[ROWS * A_DIM];
__device__ float g_h   [ROWS * FFN_DIM];

// ---------------- tf32 helpers ----------------------------------------------
__device__ __forceinline__ float tf32f(float x) {
    unsigned u;
    asm("cvt.rna.tf32.f32 %0, %1;" : "=r"(u) : "f"(x));
    return __uint_as_float(u);
}

__device__ __forceinline__ void mma_tf32(
    float& d0, float& d1, float& d2, float& d3,
    unsigned a0, unsigned a1, unsigned a2, unsigned a3,
    unsigned b0, unsigned b1)
{
    asm volatile(
        "mma.sync.aligned.m16n8k8.row.col.f32.tf32.tf32.f32 "
        "{%0,%1,%2,%3}, {%4,%5,%6,%7}, {%8,%9}, {%0,%1,%2,%3};"
        : "+f"(d0), "+f"(d1), "+f"(d2), "+f"(d3)
        : "r"(a0), "r"(a1), "r"(a2), "r"(a3), "r"(b0), "r"(b1));
}

// ---------------- block reduction (256 threads) ------------------------------
__device__ __forceinline__ float blockReduceSum256(float v) {
    __shared__ float s[8];
    __syncthreads();
#pragma unroll
    for (int o = 16; o; o >>= 1) v += __shfl_xor_sync(0xffffffffu, v, o);
    if ((threadIdx.x & 31) == 0) s[threadIdx.x >> 5] = v;
    __syncthreads();
    float r = s[0];
#pragma unroll
    for (int i = 1; i < 8; i++) r += s[i];
    return r;
}

// ---------------- tf32 MMA GEMM: 128x128 block tile, BK=32, 8 warps ---------
// C = A[M,K] @ B[K,N] + bias (opt relu). M%128==0, N%128==0, K%32==0.
// Warp grid 4(M) x 2(N): warp tile 32x64. Per-warp: 2 m-frags x 8 n-frags.
#define GAP 36     // As pitch: (4*grp+tig)%32 unique -> conflict-free
#define GBP 136    // Bs pitch: (8*tig+grp)%32 unique -> conflict-free

__device__ __forceinline__ void mma_gemm_body(
    const float* __restrict__ A, const float* __restrict__ B,
    const float* __restrict__ bias, float* __restrict__ C,
    int K, int lda, int ldb, int ldc, int relu, int m0, int n0)
{
    __shared__ float As[128 * GAP];
    __shared__ float Bs[32 * GBP];
    const int tid  = threadIdx.x;
    const int warp = tid >> 5;
    const int lane = tid & 31;
    const int grp  = lane >> 2;
    const int tig  = lane & 3;
    const int warpM = warp & 3;
    const int warpN = warp >> 2;

    float acc[2][8][4] = {};

    for (int k0 = 0; k0 < K; k0 += 32) {
        // load A tile 128x32 (tf32-converted)
#pragma unroll
        for (int it = 0; it < 4; it++) {
            int idx = tid + it * 256;
            int row = idx >> 3;
            int kq  = (idx & 7) << 2;
            float4 v = *(const float4*)(A + (size_t)(m0 + row) * lda + k0 + kq);
            As[row * GAP + kq + 0] = tf32f(v.x);
            As[row * GAP + kq + 1] = tf32f(v.y);
            As[row * GAP + kq + 2] = tf32f(v.z);
            As[row * GAP + kq + 3] = tf32f(v.w);
        }
        // load B tile 32x128 (tf32-converted)
#pragma unroll
        for (int it = 0; it < 4; it++) {
            int idx = tid + it * 256;
            int row = idx >> 5;
            int cq  = (idx & 31) << 2;
            float4 v = *(const float4*)(B + (size_t)(k0 + row) * ldb + n0 + cq);
            Bs[row * GBP + cq + 0] = tf32f(v.x);
            Bs[row * GBP + cq + 1] = tf32f(v.y);
            Bs[row * GBP + cq + 2] = tf32f(v.z);
            Bs[row * GBP + cq + 3] = tf32f(v.w);
        }
        __syncthreads();

#pragma unroll
        for (int kk = 0; kk < 4; kk++) {
            const int kc = kk * 8;
            unsigned a[2][4];
#pragma unroll
            for (int mf = 0; mf < 2; mf++) {
                const int rb = warpM * 32 + mf * 16;
                a[mf][0] = __float_as_uint(As[(rb + grp)     * GAP + kc + tig]);
                a[mf][1] = __float_as_uint(As[(rb + grp + 8) * GAP + kc + tig]);
                a[mf][2] = __float_as_uint(As[(rb + grp)     * GAP + kc + tig + 4]);
                a[mf][3] = __float_as_uint(As[(rb + grp + 8) * GAP + kc + tig + 4]);
            }
#pragma unroll
            for (int nf = 0; nf < 8; nf++) {
                const int col = warpN * 64 + nf * 8 + grp;
                unsigned b0 = __float_as_uint(Bs[(kc + tig)     * GBP + col]);
                unsigned b1 = __float_as_uint(Bs[(kc + tig + 4) * GBP + col]);
                mma_tf32(acc[0][nf][0], acc[0][nf][1], acc[0][nf][2], acc[0][nf][3],
                         a[0][0], a[0][1], a[0][2], a[0][3], b0, b1);
                mma_tf32(acc[1][nf][0], acc[1][nf][1], acc[1][nf][2], acc[1][nf][3],
                         a[1][0], a[1][1], a[1][2], a[1][3], b0, b1);
            }
        }
        __syncthreads();
    }

    // epilogue
#pragma unroll
    for (int mf = 0; mf < 2; mf++) {
        const int row = m0 + warpM * 32 + mf * 16 + grp;
#pragma unroll
        for (int nf = 0; nf < 8; nf++) {
            const int col = n0 + warpN * 64 + nf * 8 + 2 * tig;
            float bx = 0.f, by = 0.f;
            if (bias) { float2 bb = *(const float2*)(bias + col); bx = bb.x; by = bb.y; }
            float v0 = acc[mf][nf][0] + bx, v1 = acc[mf][nf][1] + by;
            float v2 = acc[mf][nf][2] + bx, v3 = acc[mf][nf][3] + by;
            if (relu) {
                v0 = fmaxf(v0, 0.f); v1 = fmaxf(v1, 0.f);
                v2 = fmaxf(v2, 0.f); v3 = fmaxf(v3, 0.f);
            }
            *(float2*)(C + (size_t)row * ldc + col)       = make_float2(v0, v1);
            *(float2*)(C + (size_t)(row + 8) * ldc + col) = make_float2(v2, v3);
        }
    }
}

__global__ void __launch_bounds__(256) k_mma_gemm(
    const float* __restrict__ A, const float* __restrict__ B,
    const float* __restrict__ bias, float* __restrict__ C,
    int K, int lda, int ldb, int ldc, int relu)
{
    mma_gemm_body(A, B, bias, C, K, lda, ldb, ldc, relu,
                  blockIdx.y * 128, blockIdx.x * 128);
}

// Fused QKV: blockIdx.z selects projection (A tile stays hot in L2)
__global__ void __launch_bounds__(256) k_mma_qkv(
    const float* __restrict__ A,
    const float* __restrict__ W0, const float* __restrict__ W1, const float* __restrict__ W2,
    const float* __restrict__ c0, const float* __restrict__ c1, const float* __restrict__ c2,
    float* __restrict__ O0, float* __restrict__ O1, float* __restrict__ O2)
{
    const float* W; const float* bb; float* O;
    if (blockIdx.z == 0)      { W = W0; bb = c0; O = O0; }
    else if (blockIdx.z == 1) { W = W1; bb = c1; O = O1; }
    else                      { W = W2; bb = c2; O = O2; }
    mma_gemm_body(A, W, bb, O, A_DIM, A_DIM, A_DIM, A_DIM, 0,
                  blockIdx.y * 128, blockIdx.x * 128);
}

// ---------------- flash attention on tensor cores ----------------------------
// Block: 128 threads (4 warps). Q-tile 64 rows (16/warp), K-tile 64 keys.
#define FQT 64
#define FKT 64
#define QP  132    // Qs/Ks pitch: (4*grp+tig)%32 unique
#define VP  136    // Vs pitch:    (8*tig+grp)%32 unique
#define PP  68     // Ps pitch:    (4*grp+tig)%32 unique
#define FLASH_SMEM ((FQT * QP + FKT * VP + FQT * PP) * 4)   // 86016 B

__global__ void __launch_bounds__(128, 2) k_flash_mma(
    const float* __restrict__ Q, const float* __restrict__ K,
    const float* __restrict__ V, float* __restrict__ Out, float alpha)
{
    const int bh = blockIdx.y;
    const size_t base = (size_t)(bh >> 1) * N_SEQ * A_DIM + (size_t)(bh & 1) * D_HEAD;
    const int q0   = blockIdx.x * FQT;
    const int tid  = threadIdx.x;
    const int warp = tid >> 5;
    const int lane = tid & 31;
    const int grp  = lane >> 2;
    const int tig  = lane & 3;
    const int rb   = warp * 16;

    extern __shared__ float sm[];
    float* Qs  = sm;                 // [64][QP]  (Q * alpha, tf32)
    float* KVs = sm + FQT * QP;      // K:[64][QP]  then V:[64][VP]
    float* Ps  = KVs + FKT * VP;     // [64][PP]

    // load Q tile (scaled, tf32)
#pragma unroll
    for (int it = 0; it < 16; it++) {
        int idx = tid + it * 128;
        int row = idx >> 5;
        int d4  = (idx & 31) << 2;
        float4 v4 = *(const float4*)(Q + base + (size_t)(q0 + row) * A_DIM + d4);
        Qs[row * QP + d4 + 0] = tf32f(v4.x * alpha);
        Qs[row * QP + d4 + 1] = tf32f(v4.y * alpha);
        Qs[row * QP + d4 + 2] = tf32f(v4.z * alpha);
        Qs[row * QP + d4 + 3] = tf32f(v4.w * alpha);
    }

    float o[16][4] = {};
    float mr0 = -1e30f, mr1 = -1e30f, l0 = 0.f, l1 = 0.f;
    __syncthreads();

    for (int t = 0; t < N_SEQ / FKT; t++) {
        const int k0 = t * FKT;
        // load K tile (tf32)
#pragma unroll
        for (int it = 0; it < 16; it++) {
            int idx = tid + it * 128;
            int row = idx >> 5;
            int d4  = (idx & 31) << 2;
            float4 v4 = *(const float4*)(K + base + (size_t)(k0 + row) * A_DIM + d4);
            KVs[row * QP + d4 + 0] = tf32f(v4.x);
            KVs[row * QP + d4 + 1] = tf32f(v4.y);
            KVs[row * QP + d4 + 2] = tf32f(v4.z);
            KVs[row * QP + d4 + 3] = tf32f(v4.w);
        }
        __syncthreads();

        // S = (alpha*Q) @ K^T : per warp 16x64, s[nf][4]
        float s[8][4] = {};
#pragma unroll
        for (int kk = 0; kk < 16; kk++) {
            const int kc = kk * 8;
            unsigned a0 = __float_as_uint(Qs[(rb + grp)     * QP + kc + tig]);
            unsigned a1 = __float_as_uint(Qs[(rb + grp + 8) * QP + kc + tig]);
            unsigned a2 = __float_as_uint(Qs[(rb + grp)     * QP + kc + tig + 4]);
            unsigned a3 = __float_as_uint(Qs[(rb + grp + 8) * QP + kc + tig + 4]);
#pragma unroll
            for (int nf = 0; nf < 8; nf++) {
                unsigned b0 = __float_as_uint(KVs[(nf * 8 + grp) * QP + kc + tig]);
                unsigned b1 = __float_as_uint(KVs[(nf * 8 + grp) * QP + kc + tig + 4]);
                mma_tf32(s[nf][0], s[nf][1], s[nf][2], s[nf][3],
                         a0, a1, a2, a3, b0, b1);
            }
        }
        __syncthreads();   // all warps done reading K tile

        // ---- online softmax (rows rb+grp and rb+grp+8) ----
        float rmax0 = -1e30f, rmax1 = -1e30f;
#pragma unroll
        for (int nf = 0; nf < 8; nf++) {
            rmax0 = fmaxf(rmax0, fmaxf(s[nf][0], s[nf][1]));
            rmax1 = fmaxf(rmax1, fmaxf(s[nf][2], s[nf][3]));
        }
#pragma unroll
        for (int w = 1; w < 4; w <<= 1) {
            rmax0 = fmaxf(rmax0, __shfl_xor_sync(0xffffffffu, rmax0, w));
            rmax1 = fmaxf(rmax1, __shfl_xor_sync(0xffffffffu, rmax1, w));
        }
        float mn0 = fmaxf(mr0, rmax0), mn1 = fmaxf(mr1, rmax1);
        float sc0 = __expf(mr0 - mn0), sc1 = __expf(mr1 - mn1);
        mr0 = mn0; mr1 = mn1;
        l0 *= sc0; l1 *= sc1;
#pragma unroll
        for (int nf = 0; nf < 16; nf++) {
            o[nf][0] *= sc0; o[nf][1] *= sc0;
            o[nf][2] *= sc1; o[nf][3] *= sc1;
        }
        float rs0 = 0.f, rs1 = 0.f;
#pragma unroll
        for (int nf = 0; nf < 8; nf++) {
            float p0 = __expf(s[nf][0] - mn0);
            float p1 = __expf(s[nf][1] - mn0);
            float p2 = __expf(s[nf][2] - mn1);
            float p3 = __expf(s[nf][3] - mn1);
            rs0 += p0 + p1; rs1 += p2 + p3;
            const int kcol = nf * 8 + 2 * tig;
            Ps[(rb + grp)     * PP + kcol]     = tf32f(p0);
            Ps[(rb + grp)     * PP + kcol + 1] = tf32f(p1);
            Ps[(rb + grp + 8) * PP + kcol]     = tf32f(p2);
            Ps[(rb + grp + 8) * PP + kcol + 1] = tf32f(p3);
        }
#pragma unroll
        for (int w = 1; w < 4; w <<= 1) {
            rs0 += __shfl_xor_sync(0xffffffffu, rs0, w);
            rs1 += __shfl_xor_sync(0xffffffffu, rs1, w);
        }
        l0 += rs0; l1 += rs1;

        // load V tile (tf32) into KVs region
#pragma unroll
        for (int it = 0; it < 16; it++) {
            int idx = tid + it * 128;
            int row = idx >> 5;
            int d4  = (idx & 31) << 2;
            float4 v4 = *(const float4*)(V + base + (size_t)(k0 + row) * A_DIM + d4);
            KVs[row * VP + d4 + 0] = tf32f(v4.x);
            KVs[row * VP + d4 + 1] = tf32f(v4.y);
            KVs[row * VP + d4 + 2] = tf32f(v4.z);
            KVs[row * VP + d4 + 3] = tf32f(v4.w);
        }
        __syncthreads();   // V ready; Ps writes visible

        // O += P @ V : per warp 16x128
#pragma unroll
        for (int kk = 0; kk < 8; kk++) {
            const int kc = kk * 8;
            unsigned a0 = __float_as_uint(Ps[(rb + grp)     * PP + kc + tig]);
            unsigned a1 = __float_as_uint(Ps[(rb + grp + 8) * PP + kc + tig]);
            unsigned a2 = __float_as_uint(Ps[(rb + grp)     * PP + kc + tig + 4]);
            unsigned a3 = __float_as_uint(Ps[(rb + grp + 8) * PP + kc + tig + 4]);
#pragma unroll
            for (int nf = 0; nf < 16; nf++) {
                unsigned b0 = __float_as_uint(KVs[(kc + tig)     * VP + nf * 8 + grp]);
                unsigned b1 = __float_as_uint(KVs[(kc + tig + 4) * VP + nf * 8 + grp]);
                mma_tf32(o[nf][0], o[nf][1], o[nf][2], o[nf][3],
                         a0, a1, a2, a3, b0, b1);
            }
        }
        __syncthreads();   // done reading V before next K overwrite
    }

    // normalize + store
    const float inv0 = 1.f / l0, inv1 = 1.f / l1;
    const int row0 = q0 + rb + grp;
#pragma unroll
    for (int nf = 0; nf < 16; nf++) {
        const int col = nf * 8 + 2 * tig;
        *(float2*)(Out + base + (size_t)row0 * A_DIM + col) =
            make_float2(o[nf][0] * inv0, o[nf][1] * inv0);
        *(float2*)(Out + base + (size_t)(row0 + 8) * A_DIM + col) =
            make_float2(o[nf][2] * inv1, o[nf][3] * inv1);
    }
}

// ---------------- LayerNorm(residual) ----------------------------------------
__global__ void k_ln_residual(const float* __restrict__ roll,
                              const float* __restrict__ prev,
                              float* __restrict__ step,
                              const float* __restrict__ g, const float* __restrict__ b)
{
    const size_t row = blockIdx.x;
    const int t = threadIdx.x;
    float x = roll[row * A_DIM + t] + prev[row * A_DIM + t];
    float mu = blockReduceSum256(x) * (1.f / A_DIM);
    float d = x - mu;
    float var = blockReduceSum256(d * d) * (1.f / A_DIM);
    step[row * A_DIM + t] = d * rsqrtf(var + LN_EPS) * g[t] + b[t];
}

// ---------------- pool + final linear ----------------------------------------
__global__ void k_pool_final(const float* __restrict__ E, const float* __restrict__ We,
                             const float* __restrict__ be, float* __restrict__ out)
{
    const int b = blockIdx.x;
    const int t = threadIdx.x;
    __shared__ float pr[A_DIM];
    const float* base = E + (size_t)b * N_SEQ * A_DIM + t;
    float s0 = 0.f, s1 = 0.f, s2 = 0.f, s3 = 0.f;
    for (int n = 0; n < N_SEQ; n += 4) {
        s0 += base[(size_t)(n + 0) * A_DIM];
        s1 += base[(size_t)(n + 1) * A_DIM];
        s2 += base[(size_t)(n + 2) * A_DIM];
        s3 += base[(size_t)(n + 3) * A_DIM];
    }
    pr[t] = (s0 + s1 + s2 + s3) * (1.f / N_SEQ);
    __syncthreads();
    float acc = 0.f;
#pragma unroll 8
    for (int k = 0; k < A_DIM; k++) acc = fmaf(pr[k], We[k * A_DIM + t], acc);
    out[b * A_DIM + t] = fmaxf(acc + be[t], 0.f);
}

// ---------------- launcher ---------------------------------------------------
extern "C" void kernel_launch(void* const* d_in, const int* in_sizes, int n_in,
                              void* d_out, int out_size)
{
    const float* X   = (const float*)d_in[0];
    const float* Wq  = (const float*)d_in[1];
    const float* bq  = (const float*)d_in[2];
    const float* Wk  = (const float*)d_in[3];
    const float* bk  = (const float*)d_in[4];
    const float* Wv  = (const float*)d_in[5];
    const float* bv  = (const float*)d_in[6];
    const float* W1  = (const float*)d_in[7];
    const float* b1  = (const float*)d_in[8];
    const float* W2  = (const float*)d_in[9];
    const float* b2  = (const float*)d_in[10];
    const float* lng = (const float*)d_in[11];
    const float* lnb = (const float*)d_in[12];
    const float* Wc  = (const float*)d_in[13];
    const float* bc  = (const float*)d_in[14];
    const float* We  = (const float*)d_in[15];
    const float* be  = (const float*)d_in[16];
    float* out = (float*)d_out;

    static float *step = nullptr, *q, *k, *v, *attn, *roll, *hbuf;
    if (!step) {
        cudaGetSymbolAddress((void**)&step, g_step);
        cudaGetSymbolAddress((void**)&q,    g_q);
        cudaGetSymbolAddress((void**)&k,    g_k);
        cudaGetSymbolAddress((void**)&v,    g_v);
        cudaGetSymbolAddress((void**)&attn, g_attn);
        cudaGetSymbolAddress((void**)&roll, g_roll);
        cudaGetSymbolAddress((void**)&hbuf, g_h);
        cudaFuncSetAttribute(k_flash_mma, cudaFuncAttributeMaxDynamicSharedMemorySize,
                             FLASH_SMEM);
    }

    const dim3 blk(256);
    const dim3 fblk(128);
    const dim3 gQKV(A_DIM / 128,   ROWS / 128, 3);   // (2, 128, 3)
    const dim3 gA  (A_DIM / 128,   ROWS / 128);      // (2, 128)
    const dim3 gF1 (FFN_DIM / 128, ROWS / 128);      // (8, 128)
    const dim3 gFl (N_SEQ / FQT, B_SZ * H_HEADS);    // (16, 32)
    const float inv_sqrt_d = 0.08838834764831845f;   // 1/sqrt(128)

    for (int i = 0; i < DEPTH; i++) {
        const float* prev = (i == 0) ? X : step;
        const size_t wo = (size_t)i * A_DIM * A_DIM;
        k_mma_qkv<<<gQKV, blk>>>(prev,
                                 Wq + wo, Wk + wo, Wv + wo,
                                 bq + i * A_DIM, bk + i * A_DIM, bv + i * A_DIM,
                                 q, k, v);
        k_flash_mma<<<gFl, fblk, FLASH_SMEM>>>(q, k, v, attn, inv_sqrt_d);
        k_mma_gemm<<<gF1, blk>>>(attn, W1 + (size_t)i * A_DIM * FFN_DIM,
                                 b1 + i * FFN_DIM, hbuf,
                                 A_DIM, A_DIM, FFN_DIM, FFN_DIM, 1);
        k_mma_gemm<<<gA, blk>>>(hbuf, W2 + (size_t)i * FFN_DIM * A_DIM,
                                b2 + i * A_DIM, roll,
                                FFN_DIM, FFN_DIM, A_DIM, A_DIM, 1);
        k_ln_residual<<<ROWS, blk>>>(roll, prev, step, lng, lnb);
    }

    // Conv1d(k=1) + ReLU -> entity encodings (reuse attn buffer)
    k_mma_gemm<<<gA, blk>>>(step, Wc, bc, attn, A_DIM, A_DIM, A_DIM, A_DIM, 1);
    // mean pool + final linear + ReLU
    k_pool_final<<<B_SZ, blk>>>(attn, We, be, out);
}

// round 6
// speedup vs baseline: 4.7111x; 1.3643x over previous
#include <cuda_runtime.h>
#include <cuda_bf16.h>
#include <math.h>

// Problem constants
#define B_SZ    16
#define N_SEQ   1024
#define H_HEADS 2
#define D_HEAD  128
#define A_DIM   256
#define FFN_DIM 1024
#define DEPTH   3
#define ROWS    (B_SZ * N_SEQ)   // 16384
#define LN_EPS  1e-5f

// ---------------- scratch (static device globals; no allocation) ------------
__device__ float g_step[ROWS * A_DIM];
__device__ float g_q   [ROWS * A_DIM];
__device__ float g_k   [ROWS * A_DIM];
__device__ float g_v   [ROWS * A_DIM];
__device__ float g_attn[ROWS * A_DIM];
__device__ float g_roll[ROWS * A_DIM];
__device__ float g_h   [ROWS * FFN_DIM];

// ---------------- bf16 helpers ----------------------------------------------
// pack two floats into bf16x2: lo -> low 16 bits, hi -> high 16 bits
__device__ __forceinline__ unsigned packbf(float lo, float hi) {
    unsigned r;
    asm("cvt.rn.bf16x2.f32 %0, %1, %2;" : "=r"(r) : "f"(hi), "f"(lo));
    return r;
}

__device__ __forceinline__ void mma_bf16(
    float& d0, float& d1, float& d2, float& d3,
    unsigned a0, unsigned a1, unsigned a2, unsigned a3,
    unsigned b0, unsigned b1)
{
    asm volatile(
        "mma.sync.aligned.m16n8k16.row.col.f32.bf16.bf16.f32 "
        "{%0,%1,%2,%3}, {%4,%5,%6,%7}, {%8,%9}, {%0,%1,%2,%3};"
        : "+f"(d0), "+f"(d1), "+f"(d2), "+f"(d3)
        : "r"(a0), "r"(a1), "r"(a2), "r"(a3), "r"(b0), "r"(b1));
}

// ---------------- block reduction (256 threads) ------------------------------
__device__ __forceinline__ float blockReduceSum256(float v) {
    __shared__ float s[8];
    __syncthreads();
#pragma unroll
    for (int o = 16; o; o >>= 1) v += __shfl_xor_sync(0xffffffffu, v, o);
    if ((threadIdx.x & 31) == 0) s[threadIdx.x >> 5] = v;
    __syncthreads();
    float r = s[0];
#pragma unroll
    for (int i = 1; i < 8; i++) r += s[i];
    return r;
}

// ---------------- bf16 MMA GEMM: 128x128 block tile, BK=32, 8 warps ---------
// C = A[M,K] @ B[K,N] + bias (opt relu). M%128==0, N%128==0, K%32==0.
// Warp grid 4(M) x 2(N): warp tile 32x64. Per-warp: 2 m-frags x 8 n-frags.
// smem holds bf16x2 words: pairs packed along K.
// PA=20: (20*grp)%32 in {0,20,8,28,16,4,24,12} + tig -> all 32 banks distinct.
// PB=136: (136*tig)%32 = 8*tig; 8*tig+grp -> distinct.
#define PA 20
#define PB 136

__device__ __forceinline__ void mma_gemm_body(
    const float* __restrict__ A, const float* __restrict__ B,
    const float* __restrict__ bias, float* __restrict__ C,
    int K, int lda, int ldb, int ldc, int relu, int m0, int n0)
{
    __shared__ unsigned As[128 * PA];   // 128 rows x 16 kpairs (+pad)
    __shared__ unsigned Bs[16 * PB];    // 16 kpairs x 128 cols (+pad)
    const int tid  = threadIdx.x;
    const int warp = tid >> 5;
    const int lane = tid & 31;
    const int grp  = lane >> 2;
    const int tig  = lane & 3;
    const int warpM = warp & 3;
    const int warpN = warp >> 2;

    float acc[2][8][4] = {};

    for (int k0 = 0; k0 < K; k0 += 32) {
        // A tile 128x32 -> bf16 pairs along k (coalesced row-major loads)
#pragma unroll
        for (int it = 0; it < 2; it++) {
            int idx = tid + it * 256;          // 0..511
            int row = idx >> 2;                // 0..127
            int p4  = (idx & 3) << 2;          // kpair 0,4,8,12
            const float* src = A + (size_t)(m0 + row) * lda + k0 + p4 * 2;
            float4 v0 = *(const float4*)(src);
            float4 v1 = *(const float4*)(src + 4);
            uint4 w;
            w.x = packbf(v0.x, v0.y);
            w.y = packbf(v0.z, v0.w);
            w.z = packbf(v1.x, v1.y);
            w.w = packbf(v1.z, v1.w);
            *(uint4*)&As[row * PA + p4] = w;
        }
        // B tile 32x128 -> pairs along k (combine rows 2kp, 2kp+1)
#pragma unroll
        for (int it = 0; it < 2; it++) {
            int idx = tid + it * 256;          // 0..511
            int kp  = idx >> 5;                // 0..15
            int n4  = (idx & 31) << 2;         // 0..124
            const float* r0 = B + (size_t)(k0 + 2 * kp)     * ldb + n0 + n4;
            const float* r1 = B + (size_t)(k0 + 2 * kp + 1) * ldb + n0 + n4;
            float4 e = *(const float4*)r0;
            float4 o = *(const float4*)r1;
            uint4 w;
            w.x = packbf(e.x, o.x);
            w.y = packbf(e.y, o.y);
            w.z = packbf(e.z, o.z);
            w.w = packbf(e.w, o.w);
            *(uint4*)&Bs[kp * PB + n4] = w;
        }
        __syncthreads();

#pragma unroll
        for (int kk = 0; kk < 2; kk++) {       // two k16 chunks
            const int kc2 = kk * 8;            // kpair base
            unsigned a[2][4];
#pragma unroll
            for (int mf = 0; mf < 2; mf++) {
                const int rb = warpM * 32 + mf * 16;
                a[mf][0] = As[(rb + grp)     * PA + kc2 + tig];
                a[mf][1] = As[(rb + grp + 8) * PA + kc2 + tig];
                a[mf][2] = As[(rb + grp)     * PA + kc2 + tig + 4];
                a[mf][3] = As[(rb + grp + 8) * PA + kc2 + tig + 4];
            }
#pragma unroll
            for (int nf = 0; nf < 8; nf++) {
                const int col = warpN * 64 + nf * 8 + grp;
                unsigned b0 = Bs[(kc2 + tig)     * PB + col];
                unsigned b1 = Bs[(kc2 + tig + 4) * PB + col];
                mma_bf16(acc[0][nf][0], acc[0][nf][1], acc[0][nf][2], acc[0][nf][3],
                         a[0][0], a[0][1], a[0][2], a[0][3], b0, b1);
                mma_bf16(acc[1][nf][0], acc[1][nf][1], acc[1][nf][2], acc[1][nf][3],
                         a[1][0], a[1][1], a[1][2], a[1][3], b0, b1);
            }
        }
        __syncthreads();
    }

    // epilogue (fp32)
#pragma unroll
    for (int mf = 0; mf < 2; mf++) {
        const int row = m0 + warpM * 32 + mf * 16 + grp;
#pragma unroll
        for (int nf = 0; nf < 8; nf++) {
            const int col = n0 + warpN * 64 + nf * 8 + 2 * tig;
            float bx = 0.f, by = 0.f;
            if (bias) { float2 bb = *(const float2*)(bias + col); bx = bb.x; by = bb.y; }
            float v0 = acc[mf][nf][0] + bx, v1 = acc[mf][nf][1] + by;
            float v2 = acc[mf][nf][2] + bx, v3 = acc[mf][nf][3] + by;
            if (relu) {
                v0 = fmaxf(v0, 0.f); v1 = fmaxf(v1, 0.f);
                v2 = fmaxf(v2, 0.f); v3 = fmaxf(v3, 0.f);
            }
            *(float2*)(C + (size_t)row * ldc + col)       = make_float2(v0, v1);
            *(float2*)(C + (size_t)(row + 8) * ldc + col) = make_float2(v2, v3);
        }
    }
}

__global__ void __launch_bounds__(256) k_mma_gemm(
    const float* __restrict__ A, const float* __restrict__ B,
    const float* __restrict__ bias, float* __restrict__ C,
    int K, int lda, int ldb, int ldc, int relu)
{
    mma_gemm_body(A, B, bias, C, K, lda, ldb, ldc, relu,
                  blockIdx.y * 128, blockIdx.x * 128);
}

// Fused QKV: blockIdx.z selects projection (A tile stays hot in L2)
__global__ void __launch_bounds__(256) k_mma_qkv(
    const float* __restrict__ A,
    const float* __restrict__ W0, const float* __restrict__ W1, const float* __restrict__ W2,
    const float* __restrict__ c0, const float* __restrict__ c1, const float* __restrict__ c2,
    float* __restrict__ O0, float* __restrict__ O1, float* __restrict__ O2)
{
    const float* W; const float* bb; float* O;
    if (blockIdx.z == 0)      { W = W0; bb = c0; O = O0; }
    else if (blockIdx.z == 1) { W = W1; bb = c1; O = O1; }
    else                      { W = W2; bb = c2; O = O2; }
    mma_gemm_body(A, W, bb, O, A_DIM, A_DIM, A_DIM, A_DIM, 0,
                  blockIdx.y * 128, blockIdx.x * 128);
}

// ---------------- flash attention on bf16 tensor cores -----------------------
// Block: 128 threads (4 warps). Q-tile 64 rows (16/warp), K-tile 64 keys.
// Qs/Ks: [row][dpair] pitch 68 ((68*grp)%32=4*grp; +tig distinct)
// Vs:    [keypair][d] pitch 136 (8*tig+grp distinct)
// Ps:    [row][keypair] pitch 36 (4*grp+tig distinct)
#define FQT 64
#define FKT 64
#define PQ  68
#define PV  136
#define PP  36

__global__ void __launch_bounds__(128, 2) k_flash_mma(
    const float* __restrict__ Q, const float* __restrict__ K,
    const float* __restrict__ V, float* __restrict__ Out, float alpha)
{
    const int bh = blockIdx.y;
    const size_t base = (size_t)(bh >> 1) * N_SEQ * A_DIM + (size_t)(bh & 1) * D_HEAD;
    const int q0   = blockIdx.x * FQT;
    const int tid  = threadIdx.x;
    const int warp = tid >> 5;
    const int lane = tid & 31;
    const int grp  = lane >> 2;
    const int tig  = lane & 3;
    const int rb   = warp * 16;

    __shared__ unsigned Qs[FQT * PQ];        // 17408 B
    __shared__ unsigned KVs[FKT * PQ];       // K:[64][68]  V:[32][136] (same 17408 B)
    __shared__ unsigned Ps[FQT * PP];        //  9216 B

    // load Q tile (scaled by alpha, bf16 pairs along d)
#pragma unroll
    for (int it = 0; it < 8; it++) {
        int idx = tid + it * 128;            // 0..1023
        int row = idx >> 4;                  // 0..63
        int dp4 = (idx & 15) << 2;           // dpair 0..60
        const float* src = Q + base + (size_t)(q0 + row) * A_DIM + dp4 * 2;
        float4 v0 = *(const float4*)(src);
        float4 v1 = *(const float4*)(src + 4);
        uint4 w;
        w.x = packbf(v0.x * alpha, v0.y * alpha);
        w.y = packbf(v0.z * alpha, v0.w * alpha);
        w.z = packbf(v1.x * alpha, v1.y * alpha);
        w.w = packbf(v1.z * alpha, v1.w * alpha);
        *(uint4*)&Qs[row * PQ + dp4] = w;
    }

    float o[16][4] = {};
    float mr0 = -1e30f, mr1 = -1e30f, l0 = 0.f, l1 = 0.f;
    __syncthreads();

    for (int t = 0; t < N_SEQ / FKT; t++) {
        const int k0 = t * FKT;
        // load K tile (bf16 pairs along d), coalesced
#pragma unroll
        for (int it = 0; it < 8; it++) {
            int idx = tid + it * 128;
            int row = idx >> 4;
            int dp4 = (idx & 15) << 2;
            const float* src = K + base + (size_t)(k0 + row) * A_DIM + dp4 * 2;
            float4 v0 = *(const float4*)(src);
            float4 v1 = *(const float4*)(src + 4);
            uint4 w;
            w.x = packbf(v0.x, v0.y);
            w.y = packbf(v0.z, v0.w);
            w.z = packbf(v1.x, v1.y);
            w.w = packbf(v1.z, v1.w);
            *(uint4*)&KVs[row * PQ + dp4] = w;
        }
        __syncthreads();

        // S = (alpha*Q) @ K^T : per warp 16x64; d=128 -> 8 k16 chunks
        float s[8][4] = {};
#pragma unroll
        for (int kk = 0; kk < 8; kk++) {
            const int kc2 = kk * 8;
            unsigned a0 = Qs[(rb + grp)     * PQ + kc2 + tig];
            unsigned a1 = Qs[(rb + grp + 8) * PQ + kc2 + tig];
            unsigned a2 = Qs[(rb + grp)     * PQ + kc2 + tig + 4];
            unsigned a3 = Qs[(rb + grp + 8) * PQ + kc2 + tig + 4];
#pragma unroll
            for (int nf = 0; nf < 8; nf++) {
                const int key = nf * 8 + grp;
                unsigned b0 = KVs[key * PQ + kc2 + tig];
                unsigned b1 = KVs[key * PQ + kc2 + tig + 4];
                mma_bf16(s[nf][0], s[nf][1], s[nf][2], s[nf][3],
                         a0, a1, a2, a3, b0, b1);
            }
        }
        __syncthreads();   // all warps done reading K tile

        // ---- online softmax (rows rb+grp and rb+grp+8) ----
        float rmax0 = -1e30f, rmax1 = -1e30f;
#pragma unroll
        for (int nf = 0; nf < 8; nf++) {
            rmax0 = fmaxf(rmax0, fmaxf(s[nf][0], s[nf][1]));
            rmax1 = fmaxf(rmax1, fmaxf(s[nf][2], s[nf][3]));
        }
#pragma unroll
        for (int w = 1; w < 4; w <<= 1) {
            rmax0 = fmaxf(rmax0, __shfl_xor_sync(0xffffffffu, rmax0, w));
            rmax1 = fmaxf(rmax1, __shfl_xor_sync(0xffffffffu, rmax1, w));
        }
        float mn0 = fmaxf(mr0, rmax0), mn1 = fmaxf(mr1, rmax1);
        float sc0 = __expf(mr0 - mn0), sc1 = __expf(mr1 - mn1);
        mr0 = mn0; mr1 = mn1;
        l0 *= sc0; l1 *= sc1;
#pragma unroll
        for (int nf = 0; nf < 16; nf++) {
            o[nf][0] *= sc0; o[nf][1] *= sc0;
            o[nf][2] *= sc1; o[nf][3] *= sc1;
        }
        float rs0 = 0.f, rs1 = 0.f;
#pragma unroll
        for (int nf = 0; nf < 8; nf++) {
            float p0 = __expf(s[nf][0] - mn0);
            float p1 = __expf(s[nf][1] - mn0);
            float p2 = __expf(s[nf][2] - mn1);
            float p3 = __expf(s[nf][3] - mn1);
            rs0 += p0 + p1; rs1 += p2 + p3;
            const int kp = nf * 4 + tig;      // keypair = (nf*8 + 2*tig)/2
            Ps[(rb + grp)     * PP + kp] = packbf(p0, p1);
            Ps[(rb + grp + 8) * PP + kp] = packbf(p2, p3);
        }
#pragma unroll
        for (int w = 1; w < 4; w <<= 1) {
            rs0 += __shfl_xor_sync(0xffffffffu, rs0, w);
            rs1 += __shfl_xor_sync(0xffffffffu, rs1, w);
        }
        l0 += rs0; l1 += rs1;

        // load V tile: pairs along key (combine rows 2kp, 2kp+1)
#pragma unroll
        for (int it = 0; it < 8; it++) {
            int idx = tid + it * 128;        // 0..1023
            int kp  = idx >> 5;              // 0..31
            int d4  = (idx & 31) << 2;       // 0..124
            const float* r0 = V + base + (size_t)(k0 + 2 * kp)     * A_DIM + d4;
            const float* r1 = V + base + (size_t)(k0 + 2 * kp + 1) * A_DIM + d4;
            float4 e = *(const float4*)r0;
            float4 od = *(const float4*)r1;
            uint4 w;
            w.x = packbf(e.x, od.x);
            w.y = packbf(e.y, od.y);
            w.z = packbf(e.z, od.z);
            w.w = packbf(e.w, od.w);
            *(uint4*)&KVs[kp * PV + d4] = w;
        }
        __syncthreads();   // V ready; Ps writes visible

        // O += P @ V : per warp 16x128; 64 keys -> 4 k16 chunks
#pragma unroll
        for (int kk = 0; kk < 4; kk++) {
            const int kc2 = kk * 8;
            unsigned a0 = Ps[(rb + grp)     * PP + kc2 + tig];
            unsigned a1 = Ps[(rb + grp + 8) * PP + kc2 + tig];
            unsigned a2 = Ps[(rb + grp)     * PP + kc2 + tig + 4];
            unsigned a3 = Ps[(rb + grp + 8) * PP + kc2 + tig + 4];
#pragma unroll
            for (int nf = 0; nf < 16; nf++) {
                const int col = nf * 8 + grp;
                unsigned b0 = KVs[(kc2 + tig)     * PV + col];
                unsigned b1 = KVs[(kc2 + tig + 4) * PV + col];
                mma_bf16(o[nf][0], o[nf][1], o[nf][2], o[nf][3],
                         a0, a1, a2, a3, b0, b1);
            }
        }
        __syncthreads();   // done reading V before next K overwrite
    }

    // normalize + store
    const float inv0 = 1.f / l0, inv1 = 1.f / l1;
    const int row0 = q0 + rb + grp;
#pragma unroll
    for (int nf = 0; nf < 16; nf++) {
        const int col = nf * 8 + 2 * tig;
        *(float2*)(Out + base + (size_t)row0 * A_DIM + col) =
            make_float2(o[nf][0] * inv0, o[nf][1] * inv0);
        *(float2*)(Out + base + (size_t)(row0 + 8) * A_DIM + col) =
            make_float2(o[nf][2] * inv1, o[nf][3] * inv1);
    }
}

// ---------------- LayerNorm(residual) ----------------------------------------
__global__ void k_ln_residual(const float* __restrict__ roll,
                              const float* __restrict__ prev,
                              float* __restrict__ step,
                              const float* __restrict__ g, const float* __restrict__ b)
{
    const size_t row = blockIdx.x;
    const int t = threadIdx.x;
    float x = roll[row * A_DIM + t] + prev[row * A_DIM + t];
    float mu = blockReduceSum256(x) * (1.f / A_DIM);
    float d = x - mu;
    float var = blockReduceSum256(d * d) * (1.f / A_DIM);
    step[row * A_DIM + t] = d * rsqrtf(var + LN_EPS) * g[t] + b[t];
}

// ---------------- pool + final linear ----------------------------------------
__global__ void k_pool_final(const float* __restrict__ E, const float* __restrict__ We,
                             const float* __restrict__ be, float* __restrict__ out)
{
    const int b = blockIdx.x;
    const int t = threadIdx.x;
    __shared__ float pr[A_DIM];
    const float* base = E + (size_t)b * N_SEQ * A_DIM + t;
    float s0 = 0.f, s1 = 0.f, s2 = 0.f, s3 = 0.f;
    for (int n = 0; n < N_SEQ; n += 4) {
        s0 += base[(size_t)(n + 0) * A_DIM];
        s1 += base[(size_t)(n + 1) * A_DIM];
        s2 += base[(size_t)(n + 2) * A_DIM];
        s3 += base[(size_t)(n + 3) * A_DIM];
    }
    pr[t] = (s0 + s1 + s2 + s3) * (1.f / N_SEQ);
    __syncthreads();
    float acc = 0.f;
#pragma unroll 8
    for (int k = 0; k < A_DIM; k++) acc = fmaf(pr[k], We[k * A_DIM + t], acc);
    out[b * A_DIM + t] = fmaxf(acc + be[t], 0.f);
}

// ---------------- launcher ---------------------------------------------------
extern "C" void kernel_launch(void* const* d_in, const int* in_sizes, int n_in,
                              void* d_out, int out_size)
{
    const float* X   = (const float*)d_in[0];
    const float* Wq  = (const float*)d_in[1];
    const float* bq  = (const float*)d_in[2];
    const float* Wk  = (const float*)d_in[3];
    const float* bk  = (const float*)d_in[4];
    const float* Wv  = (const float*)d_in[5];
    const float* bv  = (const float*)d_in[6];
    const float* W1  = (const float*)d_in[7];
    const float* b1  = (const float*)d_in[8];
    const float* W2  = (const float*)d_in[9];
    const float* b2  = (const float*)d_in[10];
    const float* lng = (const float*)d_in[11];
    const float* lnb = (const float*)d_in[12];
    const float* Wc  = (const float*)d_in[13];
    const float* bc  = (const float*)d_in[14];
    const float* We  = (const float*)d_in[15];
    const float* be  = (const float*)d_in[16];
    float* out = (float*)d_out;

    static float *step = nullptr, *q, *k, *v, *attn, *roll, *hbuf;
    if (!step) {
        cudaGetSymbolAddress((void**)&step, g_step);
        cudaGetSymbolAddress((void**)&q,    g_q);
        cudaGetSymbolAddress((void**)&k,    g_k);
        cudaGetSymbolAddress((void**)&v,    g_v);
        cudaGetSymbolAddress((void**)&attn, g_attn);
        cudaGetSymbolAddress((void**)&roll, g_roll);
        cudaGetSymbolAddress((void**)&hbuf, g_h);
    }

    const dim3 blk(256);
    const dim3 fblk(128);
    const dim3 gQKV(A_DIM / 128,   ROWS / 128, 3);   // (2, 128, 3)
    const dim3 gA  (A_DIM / 128,   ROWS / 128);      // (2, 128)
    const dim3 gF1 (FFN_DIM / 128, ROWS / 128);      // (8, 128)
    const dim3 gFl (N_SEQ / FQT, B_SZ * H_HEADS);    // (16, 32)
    const float inv_sqrt_d = 0.08838834764831845f;   // 1/sqrt(128)

    for (int i = 0; i < DEPTH; i++) {
        const float* prev = (i == 0) ? X : step;
        const size_t wo = (size_t)i * A_DIM * A_DIM;
        k_mma_qkv<<<gQKV, blk>>>(prev,
                                 Wq + wo, Wk + wo, Wv + wo,
                                 bq + i * A_DIM, bk + i * A_DIM, bv + i * A_DIM,
                                 q, k, v);
        k_flash_mma<<<gFl, fblk>>>(q, k, v, attn, inv_sqrt_d);
        k_mma_gemm<<<gF1, blk>>>(attn, W1 + (size_t)i * A_DIM * FFN_DIM,
                                 b1 + i * FFN_DIM, hbuf,
                                 A_DIM, A_DIM, FFN_DIM, FFN_DIM, 1);
        k_mma_gemm<<<gA, blk>>>(hbuf, W2 + (size_t)i * FFN_DIM * A_DIM,
                                b2 + i * A_DIM, roll,
                                FFN_DIM, FFN_DIM, A_DIM, A_DIM, 1);
        k_ln_residual<<<ROWS, blk>>>(roll, prev, step, lng, lnb);
    }

    // Conv1d(k=1) + ReLU -> entity encodings (reuse attn buffer)
    k_mma_gemm<<<gA, blk>>>(step, Wc, bc, attn, A_DIM, A_DIM, A_DIM, A_DIM, 1);
    // mean pool + final linear + ReLU
    k_pool_final<<<B_SZ, blk>>>(attn, We, be, out);
}

// round 7
// speedup vs baseline: 5.5838x; 1.1852x over previous
#include <cuda_runtime.h>
#include <math.h>

// Problem constants
#define B_SZ    16
#define N_SEQ   1024
#define H_HEADS 2
#define D_HEAD  128
#define A_DIM   256
#define FFN_DIM 1024
#define DEPTH   3
#define ROWS    (B_SZ * N_SEQ)   // 16384
#define LN_EPS  1e-5f

// ---------------- scratch (static device globals; no allocation) ------------
__device__ float g_step[ROWS * A_DIM];            // fp32 step (residual path)
__device__ float g_roll[ROWS * A_DIM];            // fp32 FFN2 output
__device__ __align__(16) unsigned gb_step[ROWS * A_DIM / 2];   // bf16x2
__device__ __align__(16) unsigned gb_q   [ROWS * A_DIM / 2];
__device__ __align__(16) unsigned gb_k   [ROWS * A_DIM / 2];
__device__ __align__(16) unsigned gb_v   [ROWS * A_DIM / 2];
__device__ __align__(16) unsigned gb_attn[ROWS * A_DIM / 2];
__device__ __align__(16) unsigned gb_h   [ROWS * FFN_DIM / 2];
// pair-packed weights: [K/2][N] bf16x2
__device__ __align__(16) unsigned gw_q[DEPTH * 128 * A_DIM];
__device__ __align__(16) unsigned gw_k[DEPTH * 128 * A_DIM];
__device__ __align__(16) unsigned gw_v[DEPTH * 128 * A_DIM];
__device__ __align__(16) unsigned gw_1[DEPTH * 128 * FFN_DIM];
__device__ __align__(16) unsigned gw_2[DEPTH * 512 * A_DIM];
__device__ __align__(16) unsigned gw_c[128 * A_DIM];

// ---------------- helpers ----------------------------------------------------
__device__ __forceinline__ unsigned packbf(float lo, float hi) {
    unsigned r;
    asm("cvt.rn.bf16x2.f32 %0, %1, %2;" : "=r"(r) : "f"(hi), "f"(lo));
    return r;
}
__device__ __forceinline__ unsigned prmtb(unsigned a, unsigned b, unsigned s) {
    unsigned r;
    asm("prmt.b32 %0,%1,%2,%3;" : "=r"(r) : "r"(a), "r"(b), "r"(s));
    return r;
}
__device__ __forceinline__ void mma_bf16(
    float& d0, float& d1, float& d2, float& d3,
    unsigned a0, unsigned a1, unsigned a2, unsigned a3,
    unsigned b0, unsigned b1)
{
    asm volatile(
        "mma.sync.aligned.m16n8k16.row.col.f32.bf16.bf16.f32 "
        "{%0,%1,%2,%3}, {%4,%5,%6,%7}, {%8,%9}, {%0,%1,%2,%3};"
        : "+f"(d0), "+f"(d1), "+f"(d2), "+f"(d3)
        : "r"(a0), "r"(a1), "r"(a2), "r"(a3), "r"(b0), "r"(b1));
}
__device__ __forceinline__ unsigned sptr(const void* p) {
    return (unsigned)__cvta_generic_to_shared(p);
}
#define CP16(dst, src) \
    asm volatile("cp.async.cg.shared.global [%0], [%1], 16;" :: "r"(dst), "l"(src))
#define CPCOMMIT() asm volatile("cp.async.commit_group;")
#define CPWAIT(n)  asm volatile("cp.async.wait_group %0;" :: "n"(n))

__device__ __forceinline__ float blockReduceSum256(float v) {
    __shared__ float s[8];
    __syncthreads();
#pragma unroll
    for (int o = 16; o; o >>= 1) v += __shfl_xor_sync(0xffffffffu, v, o);
    if ((threadIdx.x & 31) == 0) s[threadIdx.x >> 5] = v;
    __syncthreads();
    float r = s[0];
#pragma unroll
    for (int i = 1; i < 8; i++) r += s[i];
    return r;
}

// ---------------- conversion kernels -----------------------------------------
// pack fp32 [K][N] -> bf16x2 [K/2][N] (pairs along K)
__global__ void k_pack(const float* __restrict__ W, unsigned* __restrict__ out,
                       int N, int total)
{
    int i = blockIdx.x * 256 + threadIdx.x;
    if (i >= total) return;
    int kp = i / N, n = i - kp * N;
    out[i] = packbf(W[(size_t)(2 * kp) * N + n], W[(size_t)(2 * kp + 1) * N + n]);
}
// fp32 contiguous -> bf16x2 (pairs adjacent); i handles one float4 -> uint2
__global__ void k_cvt(const float* __restrict__ x, unsigned* __restrict__ y, int n4)
{
    int i = blockIdx.x * 256 + threadIdx.x;
    if (i >= n4) return;
    float4 v = *(const float4*)(x + (size_t)i * 4);
    y[2 * i]     = packbf(v.x, v.y);
    y[2 * i + 1] = packbf(v.z, v.w);
}

// ---------------- bf16 GEMM: 128x128 tile, BK=32, 8 warps, cp.async x2 ------
#define PA 20
#define PB 136
#define A_STAGE (128 * PA)
#define B_STAGE (16 * PB)

__device__ __forceinline__ void gemm_body(
    const unsigned* __restrict__ A2, const unsigned* __restrict__ Bp,
    const float* __restrict__ bias, void* Cout,
    int K, int lda2, int N, int ldc, int mode, int relu, int m0, int n0)
{
    __shared__ unsigned As[2 * A_STAGE];
    __shared__ unsigned Bs[2 * B_STAGE];
    const int tid  = threadIdx.x;
    const int warp = tid >> 5;
    const int lane = tid & 31;
    const int grp  = lane >> 2;
    const int tig  = lane & 3;
    const int warpM = warp & 3;
    const int warpN = warp >> 2;
    const int nk = K >> 5;

    // preload stage 0
    {
        unsigned sa = sptr(As), sb = sptr(Bs);
#pragma unroll
        for (int it = 0; it < 2; it++) {
            int idx = tid + it * 256;
            int row = idx >> 2, c4 = (idx & 3) << 2;
            CP16(sa + (row * PA + c4) * 4, A2 + (size_t)(m0 + row) * lda2 + c4);
        }
#pragma unroll
        for (int it = 0; it < 2; it++) {
            int idx = tid + it * 256;
            int kp = idx >> 5, n4 = (idx & 31) << 2;
            CP16(sb + (kp * PB + n4) * 4, Bp + (size_t)kp * N + n0 + n4);
        }
        CPCOMMIT();
    }

    float acc[2][8][4] = {};
    for (int i = 0; i < nk; i++) {
        if (i + 1 < nk) {
            int st = (i + 1) & 1;
            unsigned sa = sptr(As + st * A_STAGE), sb = sptr(Bs + st * B_STAGE);
            int kpn = (i + 1) * 16;
#pragma unroll
            for (int it = 0; it < 2; it++) {
                int idx = tid + it * 256;
                int row = idx >> 2, c4 = (idx & 3) << 2;
                CP16(sa + (row * PA + c4) * 4,
                     A2 + (size_t)(m0 + row) * lda2 + kpn + c4);
            }
#pragma unroll
            for (int it = 0; it < 2; it++) {
                int idx = tid + it * 256;
                int kp = idx >> 5, n4 = (idx & 31) << 2;
                CP16(sb + (kp * PB + n4) * 4, Bp + (size_t)(kpn + kp) * N + n0 + n4);
            }
            CPCOMMIT();
            CPWAIT(1);
        } else {
            CPWAIT(0);
        }
        __syncthreads();

        const unsigned* Asb = As + (i & 1) * A_STAGE;
        const unsigned* Bsb = Bs + (i & 1) * B_STAGE;
#pragma unroll
        for (int kk = 0; kk < 2; kk++) {
            const int kc2 = kk * 8;
            unsigned a[2][4];
#pragma unroll
            for (int mf = 0; mf < 2; mf++) {
                const int rb = warpM * 32 + mf * 16;
                a[mf][0] = Asb[(rb + grp)     * PA + kc2 + tig];
                a[mf][1] = Asb[(rb + grp + 8) * PA + kc2 + tig];
                a[mf][2] = Asb[(rb + grp)     * PA + kc2 + tig + 4];
                a[mf][3] = Asb[(rb + grp + 8) * PA + kc2 + tig + 4];
            }
#pragma unroll
            for (int nf = 0; nf < 8; nf++) {
                const int col = warpN * 64 + nf * 8 + grp;
                unsigned b0 = Bsb[(kc2 + tig)     * PB + col];
                unsigned b1 = Bsb[(kc2 + tig + 4) * PB + col];
                mma_bf16(acc[0][nf][0], acc[0][nf][1], acc[0][nf][2], acc[0][nf][3],
                         a[0][0], a[0][1], a[0][2], a[0][3], b0, b1);
                mma_bf16(acc[1][nf][0], acc[1][nf][1], acc[1][nf][2], acc[1][nf][3],
                         a[1][0], a[1][1], a[1][2], a[1][3], b0, b1);
            }
        }
        __syncthreads();
    }

    // epilogue
#pragma unroll
    for (int mf = 0; mf < 2; mf++) {
        const int row = m0 + warpM * 32 + mf * 16 + grp;
#pragma unroll
        for (int nf = 0; nf < 8; nf++) {
            const int col = n0 + warpN * 64 + nf * 8 + 2 * tig;
            float bx = 0.f, by = 0.f;
            if (bias) { float2 bb = *(const float2*)(bias + col); bx = bb.x; by = bb.y; }
            float v0 = acc[mf][nf][0] + bx, v1 = acc[mf][nf][1] + by;
            float v2 = acc[mf][nf][2] + bx, v3 = acc[mf][nf][3] + by;
            if (relu) {
                v0 = fmaxf(v0, 0.f); v1 = fmaxf(v1, 0.f);
                v2 = fmaxf(v2, 0.f); v3 = fmaxf(v3, 0.f);
            }
            if (mode == 0) {
                float* C = (float*)Cout;
                *(float2*)(C + (size_t)row * ldc + col)       = make_float2(v0, v1);
                *(float2*)(C + (size_t)(row + 8) * ldc + col) = make_float2(v2, v3);
            } else {
                unsigned* C2 = (unsigned*)Cout;
                const int ldc2 = ldc >> 1;
                C2[(size_t)row * ldc2 + (col >> 1)]       = packbf(v0, v1);
                C2[(size_t)(row + 8) * ldc2 + (col >> 1)] = packbf(v2, v3);
            }
        }
    }
}

__global__ void __launch_bounds__(256) k_mma_gemm(
    const unsigned* __restrict__ A2, const unsigned* __restrict__ Bp,
    const float* __restrict__ bias, void* Cout,
    int K, int lda2, int N, int ldc, int mode, int relu)
{
    gemm_body(A2, Bp, bias, Cout, K, lda2, N, ldc, mode, relu,
              blockIdx.y * 128, blockIdx.x * 128);
}

__global__ void __launch_bounds__(256) k_mma_qkv(
    const unsigned* __restrict__ A2,
    const unsigned* __restrict__ W0, const unsigned* __restrict__ W1p,
    const unsigned* __restrict__ W2p,
    const float* __restrict__ c0, const float* __restrict__ c1,
    const float* __restrict__ c2,
    unsigned* __restrict__ O0, unsigned* __restrict__ O1, unsigned* __restrict__ O2)
{
    const unsigned* W; const float* bb; unsigned* O;
    if (blockIdx.z == 0)      { W = W0;  bb = c0; O = O0; }
    else if (blockIdx.z == 1) { W = W1p; bb = c1; O = O1; }
    else                      { W = W2p; bb = c2; O = O2; }
    gemm_body(A2, W, bb, O, A_DIM, A_DIM / 2, A_DIM, A_DIM, 1, 0,
              blockIdx.y * 128, blockIdx.x * 128);
}

// ---------------- flash attention (bf16 in/out, cp.async K pipeline) ---------
#define FQT 64
#define FKT 64
#define PQ  68
#define PV  136
#define PPS 36
#define FLASH_SMEM ((64 * PQ + 64 * PQ + 32 * PV + 64 * PPS) * 4)  // 61440 B

__global__ void __launch_bounds__(128, 2) k_flash_mma(
    const unsigned* __restrict__ Q2, const unsigned* __restrict__ K2,
    const unsigned* __restrict__ V2, unsigned* __restrict__ Out2, float alpha)
{
    const int bh = blockIdx.y;
    const size_t base2 = (size_t)(bh >> 1) * N_SEQ * 128 + (size_t)(bh & 1) * 64;
    const int q0   = blockIdx.x * FQT;
    const int tid  = threadIdx.x;
    const int warp = tid >> 5;
    const int lane = tid & 31;
    const int grp  = lane >> 2;
    const int tig  = lane & 3;
    const int rb   = warp * 16;

    extern __shared__ unsigned fsm[];
    unsigned* Qs = fsm;                  // [64][PQ]
    unsigned* Ks = fsm + 64 * PQ;        // [64][PQ]
    unsigned* Vs = fsm + 128 * PQ;       // [32][PV]
    unsigned* Ps = Vs + 32 * PV;         // [64][PPS]

    // prologue: cp.async Q tile + K tile 0
    {
        unsigned sq = sptr(Qs), sk = sptr(Ks);
#pragma unroll
        for (int it = 0; it < 8; it++) {
            int idx = tid + it * 128;
            int row = idx >> 4, c4 = (idx & 15) << 2;
            CP16(sq + (row * PQ + c4) * 4, Q2 + base2 + (size_t)(q0 + row) * 128 + c4);
            CP16(sk + (row * PQ + c4) * 4, K2 + base2 + (size_t)row * 128 + c4);
        }
        CPCOMMIT();
        CPWAIT(0);
    }
    __syncthreads();

    float o[16][4] = {};
    float mr0 = -1e30f, mr1 = -1e30f, l0 = 0.f, l1 = 0.f;

    for (int t = 0; t < N_SEQ / FKT; t++) {
        const int k0 = t * FKT;

        // prefetch V tile into registers (hidden under S-mma)
        uint4 va[4], vb[4];
#pragma unroll
        for (int it = 0; it < 4; it++) {
            int idx = tid + it * 128;
            int kp = idx >> 4, dpq = idx & 15;
            const unsigned* r0 = V2 + base2 + (size_t)(k0 + 2 * kp) * 128 + dpq * 4;
            va[it] = *(const uint4*)r0;
            vb[it] = *(const uint4*)(r0 + 128);
        }

        // S = Q @ K^T (scaled later): per warp 16x64; d=128 -> 8 k16 chunks
        float s[8][4] = {};
#pragma unroll
        for (int kk = 0; kk < 8; kk++) {
            const int kc2 = kk * 8;
            unsigned a0 = Qs[(rb + grp)     * PQ + kc2 + tig];
            unsigned a1 = Qs[(rb + grp + 8) * PQ + kc2 + tig];
            unsigned a2 = Qs[(rb + grp)     * PQ + kc2 + tig + 4];
            unsigned a3 = Qs[(rb + grp + 8) * PQ + kc2 + tig + 4];
#pragma unroll
            for (int nf = 0; nf < 8; nf++) {
                const int key = nf * 8 + grp;
                unsigned b0 = Ks[key * PQ + kc2 + tig];
                unsigned b1 = Ks[key * PQ + kc2 + tig + 4];
                mma_bf16(s[nf][0], s[nf][1], s[nf][2], s[nf][3],
                         a0, a1, a2, a3, b0, b1);
            }
        }

        // store V (pair along key via prmt)
#pragma unroll
        for (int it = 0; it < 4; it++) {
            int idx = tid + it * 128;
            int kp = idx >> 4, dpq = idx & 15;
            uint4 a = va[it], b = vb[it];
            uint4 w0, w1;
            w0.x = prmtb(a.x, b.x, 0x5410u); w0.y = prmtb(a.x, b.x, 0x7632u);
            w0.z = prmtb(a.y, b.y, 0x5410u); w0.w = prmtb(a.y, b.y, 0x7632u);
            w1.x = prmtb(a.z, b.z, 0x5410u); w1.y = prmtb(a.z, b.z, 0x7632u);
            w1.z = prmtb(a.w, b.w, 0x5410u); w1.w = prmtb(a.w, b.w, 0x7632u);
            *(uint4*)&Vs[kp * PV + 8 * dpq]     = w0;
            *(uint4*)&Vs[kp * PV + 8 * dpq + 4] = w1;
        }

        // ---- online softmax ----
#pragma unroll
        for (int nf = 0; nf < 8; nf++) {
            s[nf][0] *= alpha; s[nf][1] *= alpha;
            s[nf][2] *= alpha; s[nf][3] *= alpha;
        }
        float rmax0 = -1e30f, rmax1 = -1e30f;
#pragma unroll
        for (int nf = 0; nf < 8; nf++) {
            rmax0 = fmaxf(rmax0, fmaxf(s[nf][0], s[nf][1]));
            rmax1 = fmaxf(rmax1, fmaxf(s[nf][2], s[nf][3]));
        }
#pragma unroll
        for (int w = 1; w < 4; w <<= 1) {
            rmax0 = fmaxf(rmax0, __shfl_xor_sync(0xffffffffu, rmax0, w));
            rmax1 = fmaxf(rmax1, __shfl_xor_sync(0xffffffffu, rmax1, w));
        }
        float mn0 = fmaxf(mr0, rmax0), mn1 = fmaxf(mr1, rmax1);
        float sc0 = __expf(mr0 - mn0), sc1 = __expf(mr1 - mn1);
        mr0 = mn0; mr1 = mn1;
        l0 *= sc0; l1 *= sc1;
#pragma unroll
        for (int nf = 0; nf < 16; nf++) {
            o[nf][0] *= sc0; o[nf][1] *= sc0;
            o[nf][2] *= sc1; o[nf][3] *= sc1;
        }
        float rs0 = 0.f, rs1 = 0.f;
#pragma unroll
        for (int nf = 0; nf < 8; nf++) {
            float p0 = __expf(s[nf][0] - mn0);
            float p1 = __expf(s[nf][1] - mn0);
            float p2 = __expf(s[nf][2] - mn1);
            float p3 = __expf(s[nf][3] - mn1);
            rs0 += p0 + p1; rs1 += p2 + p3;
            const int kp = nf * 4 + tig;
            Ps[(rb + grp)     * PPS + kp] = packbf(p0, p1);
            Ps[(rb + grp + 8) * PPS + kp] = packbf(p2, p3);
        }
#pragma unroll
        for (int w = 1; w < 4; w <<= 1) {
            rs0 += __shfl_xor_sync(0xffffffffu, rs0, w);
            rs1 += __shfl_xor_sync(0xffffffffu, rs1, w);
        }
        l0 += rs0; l1 += rs1;

        __syncthreads();   // Ks reads, Vs/Ps writes complete

        // overlap: fetch next K tile during PV-mma
        if (t + 1 < N_SEQ / FKT) {
            unsigned sk = sptr(Ks);
#pragma unroll
            for (int it = 0; it < 8; it++) {
                int idx = tid + it * 128;
                int row = idx >> 4, c4 = (idx & 15) << 2;
                CP16(sk + (row * PQ + c4) * 4,
                     K2 + base2 + (size_t)(k0 + FKT + row) * 128 + c4);
            }
            CPCOMMIT();
        }

        // O += P @ V : per warp 16x128; 64 keys -> 4 k16 chunks
#pragma unroll
        for (int kk = 0; kk < 4; kk++) {
            const int kc2 = kk * 8;
            unsigned a0 = Ps[(rb + grp)     * PPS + kc2 + tig];
            unsigned a1 = Ps[(rb + grp + 8) * PPS + kc2 + tig];
            unsigned a2 = Ps[(rb + grp)     * PPS + kc2 + tig + 4];
            unsigned a3 = Ps[(rb + grp + 8) * PPS + kc2 + tig + 4];
#pragma unroll
            for (int nf = 0; nf < 16; nf++) {
                const int col = nf * 8 + grp;
                unsigned b0 = Vs[(kc2 + tig)     * PV + col];
                unsigned b1 = Vs[(kc2 + tig + 4) * PV + col];
                mma_bf16(o[nf][0], o[nf][1], o[nf][2], o[nf][3],
                         a0, a1, a2, a3, b0, b1);
            }
        }

        if (t + 1 < N_SEQ / FKT) { CPWAIT(0); }
        __syncthreads();   // Vs/Ps reads done; Ks(t+1) ready
    }

    // normalize + store bf16
    const float inv0 = 1.f / l0, inv1 = 1.f / l1;
    const int row0 = q0 + rb + grp;
#pragma unroll
    for (int nf = 0; nf < 16; nf++) {
        const int c2 = nf * 4 + tig;
        Out2[base2 + (size_t)row0 * 128 + c2] =
            packbf(o[nf][0] * inv0, o[nf][1] * inv0);
        Out2[base2 + (size_t)(row0 + 8) * 128 + c2] =
            packbf(o[nf][2] * inv1, o[nf][3] * inv1);
    }
}

// ---------------- LayerNorm(residual): fp32 + bf16 dual write ----------------
__global__ void k_ln_residual(const float* __restrict__ roll,
                              const float* __restrict__ prev,
                              float* __restrict__ step, unsigned* __restrict__ step2,
                              const float* __restrict__ g, const float* __restrict__ b)
{
    const size_t row = blockIdx.x;
    const int t = threadIdx.x;
    float x = roll[row * A_DIM + t] + prev[row * A_DIM + t];
    float mu = blockReduceSum256(x) * (1.f / A_DIM);
    float d = x - mu;
    float var = blockReduceSum256(d * d) * (1.f / A_DIM);
    float y = d * rsqrtf(var + LN_EPS) * g[t] + b[t];
    step[row * A_DIM + t] = y;
    float yh = __shfl_down_sync(0xffffffffu, y, 1);
    if (!(t & 1)) step2[row * (A_DIM / 2) + (t >> 1)] = packbf(y, yh);
}

// ---------------- pool + final linear (reads bf16 E) -------------------------
__global__ void k_pool_final(const unsigned* __restrict__ E2,
                             const float* __restrict__ We,
                             const float* __restrict__ be, float* __restrict__ out)
{
    const int b = blockIdx.x;
    const int t = threadIdx.x;
    __shared__ float pr[A_DIM];
    const unsigned* base = E2 + (size_t)b * N_SEQ * 128 + (t >> 1);
    const int hi = t & 1;
    float s0 = 0.f, s1 = 0.f, s2 = 0.f, s3 = 0.f;
    for (int n = 0; n < N_SEQ; n += 4) {
        unsigned w0 = base[(size_t)(n + 0) * 128];
        unsigned w1 = base[(size_t)(n + 1) * 128];
        unsigned w2 = base[(size_t)(n + 2) * 128];
        unsigned w3 = base[(size_t)(n + 3) * 128];
        s0 += __uint_as_float(hi ? (w0 & 0xffff0000u) : (w0 << 16));
        s1 += __uint_as_float(hi ? (w1 & 0xffff0000u) : (w1 << 16));
        s2 += __uint_as_float(hi ? (w2 & 0xffff0000u) : (w2 << 16));
        s3 += __uint_as_float(hi ? (w3 & 0xffff0000u) : (w3 << 16));
    }
    pr[t] = (s0 + s1 + s2 + s3) * (1.f / N_SEQ);
    __syncthreads();
    float acc = 0.f;
#pragma unroll 8
    for (int k = 0; k < A_DIM; k++) acc = fmaf(pr[k], We[k * A_DIM + t], acc);
    out[b * A_DIM + t] = fmaxf(acc + be[t], 0.f);
}

// ---------------- launcher ---------------------------------------------------
extern "C" void kernel_launch(void* const* d_in, const int* in_sizes, int n_in,
                              void* d_out, int out_size)
{
    const float* X   = (const float*)d_in[0];
    const float* Wq  = (const float*)d_in[1];
    const float* bq  = (const float*)d_in[2];
    const float* Wk  = (const float*)d_in[3];
    const float* bk  = (const float*)d_in[4];
    const float* Wv  = (const float*)d_in[5];
    const float* bv  = (const float*)d_in[6];
    const float* W1  = (const float*)d_in[7];
    const float* b1  = (const float*)d_in[8];
    const float* W2  = (const float*)d_in[9];
    const float* b2  = (const float*)d_in[10];
    const float* lng = (const float*)d_in[11];
    const float* lnb = (const float*)d_in[12];
    const float* Wc  = (const float*)d_in[13];
    const float* bc  = (const float*)d_in[14];
    const float* We  = (const float*)d_in[15];
    const float* be  = (const float*)d_in[16];
    float* out = (float*)d_out;

    static float *step = nullptr, *roll;
    static unsigned *bstep, *bq2, *bk2, *bv2, *battn, *bh;
    static unsigned *wq, *wk, *wv, *w1, *w2, *wc;
    if (!step) {
        cudaGetSymbolAddress((void**)&step,  g_step);
        cudaGetSymbolAddress((void**)&roll,  g_roll);
        cudaGetSymbolAddress((void**)&bstep, gb_step);
        cudaGetSymbolAddress((void**)&bq2,   gb_q);
        cudaGetSymbolAddress((void**)&bk2,   gb_k);
        cudaGetSymbolAddress((void**)&bv2,   gb_v);
        cudaGetSymbolAddress((void**)&battn, gb_attn);
        cudaGetSymbolAddress((void**)&bh,    gb_h);
        cudaGetSymbolAddress((void**)&wq,    gw_q);
        cudaGetSymbolAddress((void**)&wk,    gw_k);
        cudaGetSymbolAddress((void**)&wv,    gw_v);
        cudaGetSymbolAddress((void**)&w1,    gw_1);
        cudaGetSymbolAddress((void**)&w2,    gw_2);
        cudaGetSymbolAddress((void**)&wc,    gw_c);
        cudaFuncSetAttribute(k_flash_mma,
                             cudaFuncAttributeMaxDynamicSharedMemorySize, FLASH_SMEM);
    }

    // pack weights (pairs never cross layer boundary: K even per layer)
    k_pack<<<(DEPTH * 128 * A_DIM + 255) / 256, 256>>>(Wq, wq, A_DIM, DEPTH * 128 * A_DIM);
    k_pack<<<(DEPTH * 128 * A_DIM + 255) / 256, 256>>>(Wk, wk, A_DIM, DEPTH * 128 * A_DIM);
    k_pack<<<(DEPTH * 128 * A_DIM + 255) / 256, 256>>>(Wv, wv, A_DIM, DEPTH * 128 * A_DIM);
    k_pack<<<(DEPTH * 128 * FFN_DIM + 255) / 256, 256>>>(W1, w1, FFN_DIM, DEPTH * 128 * FFN_DIM);
    k_pack<<<(DEPTH * 512 * A_DIM + 255) / 256, 256>>>(W2, w2, A_DIM, DEPTH * 512 * A_DIM);
    k_pack<<<(128 * A_DIM + 255) / 256, 256>>>(Wc, wc, A_DIM, 128 * A_DIM);
    // X -> bf16 step
    k_cvt<<<(ROWS * A_DIM / 4 + 255) / 256, 256>>>(X, bstep, ROWS * A_DIM / 4);

    const dim3 blk(256);
    const dim3 fblk(128);
    const dim3 gQKV(2, ROWS / 128, 3);
    const dim3 gA  (2, ROWS / 128);
    const dim3 gF1 (8, ROWS / 128);
    const dim3 gFl (N_SEQ / FQT, B_SZ * H_HEADS);
    const float inv_sqrt_d = 0.08838834764831845f;

    for (int i = 0; i < DEPTH; i++) {
        const float* prev = (i == 0) ? X : step;
        k_mma_qkv<<<gQKV, blk>>>(bstep,
                                 wq + (size_t)i * 128 * A_DIM,
                                 wk + (size_t)i * 128 * A_DIM,
                                 wv + (size_t)i * 128 * A_DIM,
                                 bq + i * A_DIM, bk + i * A_DIM, bv + i * A_DIM,
                                 bq2, bk2, bv2);
        k_flash_mma<<<gFl, fblk, FLASH_SMEM>>>(bq2, bk2, bv2, battn, inv_sqrt_d);
        k_mma_gemm<<<gF1, blk>>>(battn, w1 + (size_t)i * 128 * FFN_DIM,
                                 b1 + i * FFN_DIM, bh,
                                 A_DIM, A_DIM / 2, FFN_DIM, FFN_DIM, 1, 1);
        k_mma_gemm<<<gA, blk>>>(bh, w2 + (size_t)i * 512 * A_DIM,
                                b2 + i * A_DIM, roll,
                                FFN_DIM, FFN_DIM / 2, A_DIM, A_DIM, 0, 1);
        k_ln_residual<<<ROWS, blk>>>(roll, prev, step, bstep, lng, lnb);
    }

    // Conv1d(k=1) + ReLU -> bf16 entity encodings
    k_mma_gemm<<<gA, blk>>>(bstep, wc, bc, battn,
                            A_DIM, A_DIM / 2, A_DIM, A_DIM, 1, 1);
    // mean pool + final linear + ReLU
    k_pool_final<<<B_SZ, blk>>>(battn, We, be, out);
}

// round 9
// speedup vs baseline: 6.0478x; 1.0831x over previous
#include <cuda_runtime.h>
#include <math.h>

// Problem constants
#define B_SZ    16
#define N_SEQ   1024
#define H_HEADS 2
#define D_HEAD  128
#define A_DIM   256
#define FFN_DIM 1024
#define DEPTH   3
#define ROWS    (B_SZ * N_SEQ)   // 16384
#define LN_EPS  1e-5f

// ---------------- scratch (static device globals; no allocation) ------------
__device__ float g_step[ROWS * A_DIM];            // fp32 step (residual path)
__device__ __align__(16) unsigned gb_step[ROWS * A_DIM / 2];   // bf16x2
__device__ __align__(16) unsigned gb_q   [ROWS * A_DIM / 2];
__device__ __align__(16) unsigned gb_k   [ROWS * A_DIM / 2];
__device__ __align__(16) unsigned gb_v   [ROWS * A_DIM / 2];
__device__ __align__(16) unsigned gb_attn[ROWS * A_DIM / 2];
__device__ __align__(16) unsigned gb_h   [ROWS * FFN_DIM / 2];
// pair-packed weights: [K/2][N] bf16x2
__device__ __align__(16) unsigned gw_q[DEPTH * 128 * A_DIM];
__device__ __align__(16) unsigned gw_k[DEPTH * 128 * A_DIM];
__device__ __align__(16) unsigned gw_v[DEPTH * 128 * A_DIM];
__device__ __align__(16) unsigned gw_1[DEPTH * 128 * FFN_DIM];
__device__ __align__(16) unsigned gw_2[DEPTH * 512 * A_DIM];
__device__ __align__(16) unsigned gw_c[128 * A_DIM];

// ---------------- helpers ----------------------------------------------------
__device__ __forceinline__ unsigned packbf(float lo, float hi) {
    unsigned r;
    asm("cvt.rn.bf16x2.f32 %0, %1, %2;" : "=r"(r) : "f"(hi), "f"(lo));
    return r;
}
__device__ __forceinline__ unsigned prmtb(unsigned a, unsigned b, unsigned s) {
    unsigned r;
    asm("prmt.b32 %0,%1,%2,%3;" : "=r"(r) : "r"(a), "r"(b), "r"(s));
    return r;
}
__device__ __forceinline__ void mma_bf16(
    float& d0, float& d1, float& d2, float& d3,
    unsigned a0, unsigned a1, unsigned a2, unsigned a3,
    unsigned b0, unsigned b1)
{
    asm volatile(
        "mma.sync.aligned.m16n8k16.row.col.f32.bf16.bf16.f32 "
        "{%0,%1,%2,%3}, {%4,%5,%6,%7}, {%8,%9}, {%0,%1,%2,%3};"
        : "+f"(d0), "+f"(d1), "+f"(d2), "+f"(d3)
        : "r"(a0), "r"(a1), "r"(a2), "r"(a3), "r"(b0), "r"(b1));
}
__device__ __forceinline__ unsigned sptr(const void* p) {
    return (unsigned)__cvta_generic_to_shared(p);
}
#define CP16(dst, src) \
    asm volatile("cp.async.cg.shared.global [%0], [%1], 16;" :: "r"(dst), "l"(src))
#define CPCOMMIT() asm volatile("cp.async.commit_group;")
#define CPWAIT(n)  asm volatile("cp.async.wait_group %0;" :: "n"(n))

__device__ __forceinline__ float blockReduceSum256(float v) {
    __shared__ float s[8];
    __syncthreads();
#pragma unroll
    for (int o = 16; o; o >>= 1) v += __shfl_xor_sync(0xffffffffu, v, o);
    if ((threadIdx.x & 31) == 0) s[threadIdx.x >> 5] = v;
    __syncthreads();
    float r = s[0];
#pragma unroll
    for (int i = 1; i < 8; i++) r += s[i];
    return r;
}

// ---------------- fused pack/convert kernel -----------------------------------
// segments (element counts):
//  wq/wk/wv: 98304 each | w1: 393216 | w2: 393216 | wc: 32768 | X: 1048576 f4
#define SEG_Q  98304
#define SEG_1  393216
#define SEG_2  393216
#define SEG_C  32768
#define PACK_TOTAL (3 * SEG_Q + SEG_1 + SEG_2 + SEG_C)       // 1114112
#define CVT_TOTAL  (ROWS * A_DIM / 4)                        // 1048576
__global__ void k_pack_all(
    const float* __restrict__ Wq, const float* __restrict__ Wk,
    const float* __restrict__ Wv, const float* __restrict__ W1,
    const float* __restrict__ W2, const float* __restrict__ Wc,
    const float* __restrict__ X,
    unsigned* __restrict__ wq, unsigned* __restrict__ wk, unsigned* __restrict__ wv,
    unsigned* __restrict__ w1, unsigned* __restrict__ w2, unsigned* __restrict__ wc,
    unsigned* __restrict__ bstep)
{
    int i = blockIdx.x * 256 + threadIdx.x;
    if (i < PACK_TOTAL) {
        const float* src; unsigned* dst; int N, j = i;
        if (j < 3 * SEG_Q) {
            int s = j / SEG_Q; j -= s * SEG_Q;
            src = (s == 0) ? Wq : (s == 1) ? Wk : Wv;
            dst = (s == 0) ? wq : (s == 1) ? wk : wv;
            N = A_DIM;
        } else if ((j -= 3 * SEG_Q) < SEG_1) {
            src = W1; dst = w1; N = FFN_DIM;
        } else if ((j -= SEG_1) < SEG_2) {
            src = W2; dst = w2; N = A_DIM;
        } else {
            j -= SEG_2; src = Wc; dst = wc; N = A_DIM;
        }
        int kp = j / N, n = j - kp * N;
        dst[j] = packbf(src[(size_t)(2 * kp) * N + n], src[(size_t)(2 * kp + 1) * N + n]);
    } else {
        int j = i - PACK_TOTAL;
        if (j < CVT_TOTAL) {
            float4 v = *(const float4*)(X + (size_t)j * 4);
            bstep[2 * j]     = packbf(v.x, v.y);
            bstep[2 * j + 1] = packbf(v.z, v.w);
        }
    }
}

// ---------------- bf16 GEMM: 128x128 tile, BK=32, 8 warps, cp.async x2 ------
#define PA 20
#define PB 136
#define A_STAGE (128 * PA)
#define B_STAGE (16 * PB)

__device__ __forceinline__ void gemm_body(
    const unsigned* __restrict__ A2, const unsigned* __restrict__ Bp,
    const float* __restrict__ bias, void* Cout,
    int K, int lda2, int N, int ldc, int mode, int relu, int m0, int n0)
{
    __shared__ unsigned As[2 * A_STAGE];
    __shared__ unsigned Bs[2 * B_STAGE];
    const int tid  = threadIdx.x;
    const int warp = tid >> 5;
    const int lane = tid & 31;
    const int grp  = lane >> 2;
    const int tig  = lane & 3;
    const int warpM = warp & 3;
    const int warpN = warp >> 2;
    const int nk = K >> 5;

    {
        unsigned sa = sptr(As), sb = sptr(Bs);
#pragma unroll
        for (int it = 0; it < 2; it++) {
            int idx = tid + it * 256;
            int row = idx >> 2, c4 = (idx & 3) << 2;
            CP16(sa + (row * PA + c4) * 4, A2 + (size_t)(m0 + row) * lda2 + c4);
        }
#pragma unroll
        for (int it = 0; it < 2; it++) {
            int idx = tid + it * 256;
            int kp = idx >> 5, n4 = (idx & 31) << 2;
            CP16(sb + (kp * PB + n4) * 4, Bp + (size_t)kp * N + n0 + n4);
        }
        CPCOMMIT();
    }

    float acc[2][8][4] = {};
    for (int i = 0; i < nk; i++) {
        if (i + 1 < nk) {
            int st = (i + 1) & 1;
            unsigned sa = sptr(As + st * A_STAGE), sb = sptr(Bs + st * B_STAGE);
            int kpn = (i + 1) * 16;
#pragma unroll
            for (int it = 0; it < 2; it++) {
                int idx = tid + it * 256;
                int row = idx >> 2, c4 = (idx & 3) << 2;
                CP16(sa + (row * PA + c4) * 4,
                     A2 + (size_t)(m0 + row) * lda2 + kpn + c4);
            }
#pragma unroll
            for (int it = 0; it < 2; it++) {
                int idx = tid + it * 256;
                int kp = idx >> 5, n4 = (idx & 31) << 2;
                CP16(sb + (kp * PB + n4) * 4, Bp + (size_t)(kpn + kp) * N + n0 + n4);
            }
            CPCOMMIT();
            CPWAIT(1);
        } else {
            CPWAIT(0);
        }
        __syncthreads();

        const unsigned* Asb = As + (i & 1) * A_STAGE;
        const unsigned* Bsb = Bs + (i & 1) * B_STAGE;
#pragma unroll
        for (int kk = 0; kk < 2; kk++) {
            const int kc2 = kk * 8;
            unsigned a[2][4];
#pragma unroll
            for (int mf = 0; mf < 2; mf++) {
                const int rb = warpM * 32 + mf * 16;
                a[mf][0] = Asb[(rb + grp)     * PA + kc2 + tig];
                a[mf][1] = Asb[(rb + grp + 8) * PA + kc2 + tig];
                a[mf][2] = Asb[(rb + grp)     * PA + kc2 + tig + 4];
                a[mf][3] = Asb[(rb + grp + 8) * PA + kc2 + tig + 4];
            }
#pragma unroll
            for (int nf = 0; nf < 8; nf++) {
                const int col = warpN * 64 + nf * 8 + grp;
                unsigned b0 = Bsb[(kc2 + tig)     * PB + col];
                unsigned b1 = Bsb[(kc2 + tig + 4) * PB + col];
                mma_bf16(acc[0][nf][0], acc[0][nf][1], acc[0][nf][2], acc[0][nf][3],
                         a[0][0], a[0][1], a[0][2], a[0][3], b0, b1);
                mma_bf16(acc[1][nf][0], acc[1][nf][1], acc[1][nf][2], acc[1][nf][3],
                         a[1][0], a[1][1], a[1][2], a[1][3], b0, b1);
            }
        }
        __syncthreads();
    }

#pragma unroll
    for (int mf = 0; mf < 2; mf++) {
        const int row = m0 + warpM * 32 + mf * 16 + grp;
#pragma unroll
        for (int nf = 0; nf < 8; nf++) {
            const int col = n0 + warpN * 64 + nf * 8 + 2 * tig;
            float bx = 0.f, by = 0.f;
            if (bias) { float2 bb = *(const float2*)(bias + col); bx = bb.x; by = bb.y; }
            float v0 = acc[mf][nf][0] + bx, v1 = acc[mf][nf][1] + by;
            float v2 = acc[mf][nf][2] + bx, v3 = acc[mf][nf][3] + by;
            if (relu) {
                v0 = fmaxf(v0, 0.f); v1 = fmaxf(v1, 0.f);
                v2 = fmaxf(v2, 0.f); v3 = fmaxf(v3, 0.f);
            }
            if (mode == 0) {
                float* C = (float*)Cout;
                *(float2*)(C + (size_t)row * ldc + col)       = make_float2(v0, v1);
                *(float2*)(C + (size_t)(row + 8) * ldc + col) = make_float2(v2, v3);
            } else {
                unsigned* C2 = (unsigned*)Cout;
                const int ldc2 = ldc >> 1;
                C2[(size_t)row * ldc2 + (col >> 1)]       = packbf(v0, v1);
                C2[(size_t)(row + 8) * ldc2 + (col >> 1)] = packbf(v2, v3);
            }
        }
    }
}

__global__ void __launch_bounds__(256) k_mma_gemm(
    const unsigned* __restrict__ A2, const unsigned* __restrict__ Bp,
    const float* __restrict__ bias, void* Cout,
    int K, int lda2, int N, int ldc, int mode, int relu)
{
    gemm_body(A2, Bp, bias, Cout, K, lda2, N, ldc, mode, relu,
              blockIdx.y * 128, blockIdx.x * 128);
}

__global__ void __launch_bounds__(256) k_mma_qkv(
    const unsigned* __restrict__ A2,
    const unsigned* __restrict__ W0, const unsigned* __restrict__ W1p,
    const unsigned* __restrict__ W2p,
    const float* __restrict__ c0, const float* __restrict__ c1,
    const float* __restrict__ c2,
    unsigned* __restrict__ O0, unsigned* __restrict__ O1, unsigned* __restrict__ O2)
{
    const unsigned* W; const float* bb; unsigned* O;
    if (blockIdx.z == 0)      { W = W0;  bb = c0; O = O0; }
    else if (blockIdx.z == 1) { W = W1p; bb = c1; O = O1; }
    else                      { W = W2p; bb = c2; O = O2; }
    gemm_body(A2, W, bb, O, A_DIM, A_DIM / 2, A_DIM, A_DIM, 1, 0,
              blockIdx.y * 128, blockIdx.x * 128);
}

// ---------------- fused FFN2 + bias + relu + residual + LayerNorm ------------
// Tile 64 rows x 256 cols (full row per block). 8 warps: warpM(2) x warpN(4).
#define F2PA 20
#define F2PB 264     // (264*tig)%32 = 8*tig -> conflict-free
#define F2_AS (64 * F2PA)
#define F2_BS (16 * F2PB)

__global__ void __launch_bounds__(256, 2) k_ffn2_ln(
    const unsigned* __restrict__ A2,      // bh [ROWS][512]
    const unsigned* __restrict__ Bp,      // w2 layer [512][256]
    const float* __restrict__ bias,       // b2 layer
    const float* __restrict__ prev,       // residual input fp32
    float* __restrict__ step, unsigned* __restrict__ step2,
    const float* __restrict__ g, const float* __restrict__ b)
{
    __shared__ unsigned As[2 * F2_AS];
    __shared__ unsigned Bs[2 * F2_BS];
    __shared__ float reds[4][64], redq[4][64];
    const int tid  = threadIdx.x;
    const int warp = tid >> 5;
    const int lane = tid & 31;
    const int grp  = lane >> 2;
    const int tig  = lane & 3;
    const int warpM = warp & 1;
    const int warpN = warp >> 1;
    const int m0 = blockIdx.x * 64;
    const int nk = FFN_DIM / 32;          // 32

    {
        unsigned sa = sptr(As), sb = sptr(Bs);
        {   // A: 64 rows x 16 pairs = 256 uint4
            int row = tid >> 2, c4 = (tid & 3) << 2;
            CP16(sa + (row * F2PA + c4) * 4, A2 + (size_t)(m0 + row) * 512 + c4);
        }
#pragma unroll
        for (int it = 0; it < 4; it++) {  // B: 16 x 256 = 1024 uint4
            int idx = tid + it * 256;
            int kp = idx >> 6, n4 = (idx & 63) << 2;
            CP16(sb + (kp * F2PB + n4) * 4, Bp + (size_t)kp * A_DIM + n4);
        }
        CPCOMMIT();
    }

    float acc[2][8][4] = {};
    for (int i = 0; i < nk; i++) {
        if (i + 1 < nk) {
            int st = (i + 1) & 1;
            unsigned sa = sptr(As + st * F2_AS), sb = sptr(Bs + st * F2_BS);
            int kpn = (i + 1) * 16;
            {
                int row = tid >> 2, c4 = (tid & 3) << 2;
                CP16(sa + (row * F2PA + c4) * 4,
                     A2 + (size_t)(m0 + row) * 512 + kpn + c4);
            }
#pragma unroll
            for (int it = 0; it < 4; it++) {
                int idx = tid + it * 256;
                int kp = idx >> 6, n4 = (idx & 63) << 2;
                CP16(sb + (kp * F2PB + n4) * 4, Bp + (size_t)(kpn + kp) * A_DIM + n4);
            }
            CPCOMMIT();
            CPWAIT(1);
        } else {
            CPWAIT(0);
        }
        __syncthreads();

        const unsigned* Asb = As + (i & 1) * F2_AS;
        const unsigned* Bsb = Bs + (i & 1) * F2_BS;
#pragma unroll
        for (int kk = 0; kk < 2; kk++) {
            const int kc2 = kk * 8;
            unsigned a[2][4];
#pragma unroll
            for (int mf = 0; mf < 2; mf++) {
                const int rb = warpM * 32 + mf * 16;
                a[mf][0] = Asb[(rb + grp)     * F2PA + kc2 + tig];
                a[mf][1] = Asb[(rb + grp + 8) * F2PA + kc2 + tig];
                a[mf][2] = Asb[(rb + grp)     * F2PA + kc2 + tig + 4];
                a[mf][3] = Asb[(rb + grp + 8) * F2PA + kc2 + tig + 4];
            }
#pragma unroll
            for (int nf = 0; nf < 8; nf++) {
                const int col = warpN * 64 + nf * 8 + grp;
                unsigned b0 = Bsb[(kc2 + tig)     * F2PB + col];
                unsigned b1 = Bsb[(kc2 + tig + 4) * F2PB + col];
                mma_bf16(acc[0][nf][0], acc[0][nf][1], acc[0][nf][2], acc[0][nf][3],
                         a[0][0], a[0][1], a[0][2], a[0][3], b0, b1);
                mma_bf16(acc[1][nf][0], acc[1][nf][1], acc[1][nf][2], acc[1][nf][3],
                         a[1][0], a[1][1], a[1][2], a[1][3], b0, b1);
            }
        }
        __syncthreads();
    }

    // ---- epilogue: bias + relu + residual, partial LN stats ----
#pragma unroll
    for (int mf = 0; mf < 2; mf++) {
#pragma unroll
        for (int half = 0; half < 2; half++) {
            const int rloc = warpM * 32 + mf * 16 + half * 8 + grp;
            const int row  = m0 + rloc;
            const int ai   = half * 2;
            float sum = 0.f, sq = 0.f;
#pragma unroll
            for (int nf = 0; nf < 8; nf++) {
                const int col = warpN * 64 + nf * 8 + 2 * tig;
                float2 bb = *(const float2*)(bias + col);
                float2 pv = *(const float2*)(prev + (size_t)row * A_DIM + col);
                float v0 = fmaxf(acc[mf][nf][ai]     + bb.x, 0.f) + pv.x;
                float v1 = fmaxf(acc[mf][nf][ai + 1] + bb.y, 0.f) + pv.y;
                acc[mf][nf][ai] = v0; acc[mf][nf][ai + 1] = v1;
                sum += v0 + v1;
                sq  += v0 * v0 + v1 * v1;
            }
            sum += __shfl_xor_sync(0xffffffffu, sum, 1);
            sum += __shfl_xor_sync(0xffffffffu, sum, 2);
            sq  += __shfl_xor_sync(0xffffffffu, sq, 1);
            sq  += __shfl_xor_sync(0xffffffffu, sq, 2);
            if (tig == 0) { reds[warpN][rloc] = sum; redq[warpN][rloc] = sq; }
        }
    }
    __syncthreads();

    // ---- finish LN and write fp32 + bf16 ----
#pragma unroll
    for (int mf = 0; mf < 2; mf++) {
#pragma unroll
        for (int half = 0; half < 2; half++) {
            const int rloc = warpM * 32 + mf * 16 + half * 8 + grp;
            const int row  = m0 + rloc;
            const int ai   = half * 2;
            float s = reds[0][rloc] + reds[1][rloc] + reds[2][rloc] + reds[3][rloc];
            float q = redq[0][rloc] + redq[1][rloc] + redq[2][rloc] + redq[3][rloc];
            float mu  = s * (1.f / A_DIM);
            float var = q * (1.f / A_DIM) - mu * mu;
            float rs  = rsqrtf(var + LN_EPS);
#pragma unroll
            for (int nf = 0; nf < 8; nf++) {
                const int col = warpN * 64 + nf * 8 + 2 * tig;
                float2 gg = *(const float2*)(g + col);
                float2 b2v = *(const float2*)(b + col);
                float y0 = (acc[mf][nf][ai]     - mu) * rs * gg.x + b2v.x;
                float y1 = (acc[mf][nf][ai + 1] - mu) * rs * gg.y + b2v.y;
                *(float2*)(step + (size_t)row * A_DIM + col) = make_float2(y0, y1);
                step2[(size_t)row * (A_DIM / 2) + (col >> 1)] = packbf(y0, y1);
            }
        }
    }
}

// ---------------- flash attention (bf16 in/out, cp.async K pipeline) ---------
#define FQT 64
#define FKT 64
#define PQ  68
#define PV  136
#define PPS 36
#define FLASH_SMEM ((64 * PQ + 64 * PQ + 32 * PV + 64 * PPS) * 4)  // 61440 B

__global__ void __launch_bounds__(128, 2) k_flash_mma(
    const unsigned* __restrict__ Q2, const unsigned* __restrict__ K2,
    const unsigned* __restrict__ V2, unsigned* __restrict__ Out2, float alpha)
{
    const int bh = blockIdx.y;
    const size_t base2 = (size_t)(bh >> 1) * N_SEQ * 128 + (size_t)(bh & 1) * 64;
    const int q0   = blockIdx.x * FQT;
    const int tid  = threadIdx.x;
    const int warp = tid >> 5;
    const int lane = tid & 31;
    const int grp  = lane >> 2;
    const int tig  = lane & 3;
    const int rb   = warp * 16;

    extern __shared__ unsigned fsm[];
    unsigned* Qs = fsm;
    unsigned* Ks = fsm + 64 * PQ;
    unsigned* Vs = fsm + 128 * PQ;
    unsigned* Ps = Vs + 32 * PV;

    {
        unsigned sq = sptr(Qs), sk = sptr(Ks);
#pragma unroll
        for (int it = 0; it < 8; it++) {
            int idx = tid + it * 128;
            int row = idx >> 4, c4 = (idx & 15) << 2;
            CP16(sq + (row * PQ + c4) * 4, Q2 + base2 + (size_t)(q0 + row) * 128 + c4);
            CP16(sk + (row * PQ + c4) * 4, K2 + base2 + (size_t)row * 128 + c4);
        }
        CPCOMMIT();
        CPWAIT(0);
    }
    __syncthreads();

    float o[16][4] = {};
    float mr0 = -1e30f, mr1 = -1e30f, l0 = 0.f, l1 = 0.f;

    for (int t = 0; t < N_SEQ / FKT; t++) {
        const int k0 = t * FKT;

        uint4 va[4], vb[4];
#pragma unroll
        for (int it = 0; it < 4; it++) {
            int idx = tid + it * 128;
            int kp = idx >> 4, dpq = idx & 15;
            const unsigned* r0 = V2 + base2 + (size_t)(k0 + 2 * kp) * 128 + dpq * 4;
            va[it] = *(const uint4*)r0;
            vb[it] = *(const uint4*)(r0 + 128);
        }

        float s[8][4] = {};
#pragma unroll
        for (int kk = 0; kk < 8; kk++) {
            const int kc2 = kk * 8;
            unsigned a0 = Qs[(rb + grp)     * PQ + kc2 + tig];
            unsigned a1 = Qs[(rb + grp + 8) * PQ + kc2 + tig];
            unsigned a2 = Qs[(rb + grp)     * PQ + kc2 + tig + 4];
            unsigned a3 = Qs[(rb + grp + 8) * PQ + kc2 + tig + 4];
#pragma unroll
            for (int nf = 0; nf < 8; nf++) {
                const int key = nf * 8 + grp;
                unsigned b0 = Ks[key * PQ + kc2 + tig];
                unsigned b1 = Ks[key * PQ + kc2 + tig + 4];
                mma_bf16(s[nf][0], s[nf][1], s[nf][2], s[nf][3],
                         a0, a1, a2, a3, b0, b1);
            }
        }

#pragma unroll
        for (int it = 0; it < 4; it++) {
            int idx = tid + it * 128;
            int kp = idx >> 4, dpq = idx & 15;
            uint4 a = va[it], bbv = vb[it];
            uint4 w0, w1;
            w0.x = prmtb(a.x, bbv.x, 0x5410u); w0.y = prmtb(a.x, bbv.x, 0x7632u);
            w0.z = prmtb(a.y, bbv.y, 0x5410u); w0.w = prmtb(a.y, bbv.y, 0x7632u);
            w1.x = prmtb(a.z, bbv.z, 0x5410u); w1.y = prmtb(a.z, bbv.z, 0x7632u);
            w1.z = prmtb(a.w, bbv.w, 0x5410u); w1.w = prmtb(a.w, bbv.w, 0x7632u);
            *(uint4*)&Vs[kp * PV + 8 * dpq]     = w0;
            *(uint4*)&Vs[kp * PV + 8 * dpq + 4] = w1;
        }

#pragma unroll
        for (int nf = 0; nf < 8; nf++) {
            s[nf][0] *= alpha; s[nf][1] *= alpha;
            s[nf][2] *= alpha; s[nf][3] *= alpha;
        }
        float rmax0 = -1e30f, rmax1 = -1e30f;
#pragma unroll
        for (int nf = 0; nf < 8; nf++) {
            rmax0 = fmaxf(rmax0, fmaxf(s[nf][0], s[nf][1]));
            rmax1 = fmaxf(rmax1, fmaxf(s[nf][2], s[nf][3]));
        }
#pragma unroll
        for (int w = 1; w < 4; w <<= 1) {
            rmax0 = fmaxf(rmax0, __shfl_xor_sync(0xffffffffu, rmax0, w));
            rmax1 = fmaxf(rmax1, __shfl_xor_sync(0xffffffffu, rmax1, w));
        }
        float mn0 = fmaxf(mr0, rmax0), mn1 = fmaxf(mr1, rmax1);
        float sc0 = __expf(mr0 - mn0), sc1 = __expf(mr1 - mn1);
        mr0 = mn0; mr1 = mn1;
        l0 *= sc0; l1 *= sc1;
#pragma unroll
        for (int nf = 0; nf < 16; nf++) {
            o[nf][0] *= sc0; o[nf][1] *= sc0;
            o[nf][2] *= sc1; o[nf][3] *= sc1;
        }
        float rs0 = 0.f, rs1 = 0.f;
#pragma unroll
        for (int nf = 0; nf < 8; nf++) {
            float p0 = __expf(s[nf][0] - mn0);
            float p1 = __expf(s[nf][1] - mn0);
            float p2 = __expf(s[nf][2] - mn1);
            float p3 = __expf(s[nf][3] - mn1);
            rs0 += p0 + p1; rs1 += p2 + p3;
            const int kp = nf * 4 + tig;
            Ps[(rb + grp)     * PPS + kp] = packbf(p0, p1);
            Ps[(rb + grp + 8) * PPS + kp] = packbf(p2, p3);
        }
#pragma unroll
        for (int w = 1; w < 4; w <<= 1) {
            rs0 += __shfl_xor_sync(0xffffffffu, rs0, w);
            rs1 += __shfl_xor_sync(0xffffffffu, rs1, w);
        }
        l0 += rs0; l1 += rs1;

        __syncthreads();

        if (t + 1 < N_SEQ / FKT) {
            unsigned sk = sptr(Ks);
#pragma unroll
            for (int it = 0; it < 8; it++) {
                int idx = tid + it * 128;
                int row = idx >> 4, c4 = (idx & 15) << 2;
                CP16(sk + (row * PQ + c4) * 4,
                     K2 + base2 + (size_t)(k0 + FKT + row) * 128 + c4);
            }
            CPCOMMIT();
        }

#pragma unroll
        for (int kk = 0; kk < 4; kk++) {
            const int kc2 = kk * 8;
            unsigned a0 = Ps[(rb + grp)     * PPS + kc2 + tig];
            unsigned a1 = Ps[(rb + grp + 8) * PPS + kc2 + tig];
            unsigned a2 = Ps[(rb + grp)     * PPS + kc2 + tig + 4];
            unsigned a3 = Ps[(rb + grp + 8) * PPS + kc2 + tig + 4];
#pragma unroll
            for (int nf = 0; nf < 16; nf++) {
                const int col = nf * 8 + grp;
                unsigned b0 = Vs[(kc2 + tig)     * PV + col];
                unsigned b1 = Vs[(kc2 + tig + 4) * PV + col];
                mma_bf16(o[nf][0], o[nf][1], o[nf][2], o[nf][3],
                         a0, a1, a2, a3, b0, b1);
            }
        }

        if (t + 1 < N_SEQ / FKT) { CPWAIT(0); }
        __syncthreads();
    }

    const float inv0 = 1.f / l0, inv1 = 1.f / l1;
    const int row0 = q0 + rb + grp;
#pragma unroll
    for (int nf = 0; nf < 16; nf++) {
        const int c2 = nf * 4 + tig;
        Out2[base2 + (size_t)row0 * 128 + c2] =
            packbf(o[nf][0] * inv0, o[nf][1] * inv0);
        Out2[base2 + (size_t)(row0 + 8) * 128 + c2] =
            packbf(o[nf][2] * inv1, o[nf][3] * inv1);
    }
}

// ---------------- pool + final linear (reads bf16 E) -------------------------
__global__ void k_pool_final(const unsigned* __restrict__ E2,
                             const float* __restrict__ We,
                             const float* __restrict__ be, float* __restrict__ out)
{
    const int b = blockIdx.x;
    const int t = threadIdx.x;
    __shared__ float pr[A_DIM];
    const unsigned* base = E2 + (size_t)b * N_SEQ * 128 + (t >> 1);
    const int hi = t & 1;
    float s0 = 0.f, s1 = 0.f, s2 = 0.f, s3 = 0.f;
    for (int n = 0; n < N_SEQ; n += 4) {
        unsigned w0 = base[(size_t)(n + 0) * 128];
        unsigned w1 = base[(size_t)(n + 1) * 128];
        unsigned w2 = base[(size_t)(n + 2) * 128];
        unsigned w3 = base[(size_t)(n + 3) * 128];
        s0 += __uint_as_float(hi ? (w0 & 0xffff0000u) : (w0 << 16));
        s1 += __uint_as_float(hi ? (w1 & 0xffff0000u) : (w1 << 16));
        s2 += __uint_as_float(hi ? (w2 & 0xffff0000u) : (w2 << 16));
        s3 += __uint_as_float(hi ? (w3 & 0xffff0000u) : (w3 << 16));
    }
    pr[t] = (s0 + s1 + s2 + s3) * (1.f / N_SEQ);
    __syncthreads();
    float acc = 0.f;
#pragma unroll 8
    for (int k = 0; k < A_DIM; k++) acc = fmaf(pr[k], We[k * A_DIM + t], acc);
    out[b * A_DIM + t] = fmaxf(acc + be[t], 0.f);
}

// ---------------- launcher ---------------------------------------------------
extern "C" void kernel_launch(void* const* d_in, const int* in_sizes, int n_in,
                              void* d_out, int out_size)
{
    const float* X   = (const float*)d_in[0];
    const float* Wq  = (const float*)d_in[1];
    const float* bq  = (const float*)d_in[2];
    const float* Wk  = (const float*)d_in[3];
    const float* bk  = (const float*)d_in[4];
    const float* Wv  = (const float*)d_in[5];
    const float* bv  = (const float*)d_in[6];
    const float* W1  = (const float*)d_in[7];
    const float* b1  = (const float*)d_in[8];
    const float* W2  = (const float*)d_in[9];
    const float* b2  = (const float*)d_in[10];
    const float* lng = (const float*)d_in[11];
    const float* lnb = (const float*)d_in[12];
    const float* Wc  = (const float*)d_in[13];
    const float* bc  = (const float*)d_in[14];
    const float* We  = (const float*)d_in[15];
    const float* be  = (const float*)d_in[16];
    float* out = (float*)d_out;

    static float *step = nullptr;
    static unsigned *bstep, *bq2, *bk2, *bv2, *battn, *bh;
    static unsigned *wq, *wk, *wv, *w1, *w2, *wc;
    if (!step) {
        cudaGetSymbolAddress((void**)&step,  g_step);
        cudaGetSymbolAddress((void**)&bstep, gb_step);
        cudaGetSymbolAddress((void**)&bq2,   gb_q);
        cudaGetSymbolAddress((void**)&bk2,   gb_k);
        cudaGetSymbolAddress((void**)&bv2,   gb_v);
        cudaGetSymbolAddress((void**)&battn, gb_attn);
        cudaGetSymbolAddress((void**)&bh,    gb_h);
        cudaGetSymbolAddress((void**)&wq,    gw_q);
        cudaGetSymbolAddress((void**)&wk,    gw_k);
        cudaGetSymbolAddress((void**)&wv,    gw_v);
        cudaGetSymbolAddress((void**)&w1,    gw_1);
        cudaGetSymbolAddress((void**)&w2,    gw_2);
        cudaGetSymbolAddress((void**)&wc,    gw_c);
        cudaFuncSetAttribute(k_flash_mma,
                             cudaFuncAttributeMaxDynamicSharedMemorySize, FLASH_SMEM);
    }

    // one fused pack+convert launch
    {
        int total = PACK_TOTAL + CVT_TOTAL;
        k_pack_all<<<(total + 255) / 256, 256>>>(Wq, Wk, Wv, W1, W2, Wc, X,
                                                 wq, wk, wv, w1, w2, wc, bstep);
    }

    const dim3 blk(256);
    const dim3 fblk(128);
    const dim3 gQKV(2, ROWS / 128, 3);
    const dim3 gF1 (8, ROWS / 128);
    const dim3 gA  (2, ROWS / 128);
    const dim3 gFl (N_SEQ / FQT, B_SZ * H_HEADS);
    const float inv_sqrt_d = 0.08838834764831845f;

    for (int i = 0; i < DEPTH; i++) {
        const float* prev = (i == 0) ? X : step;
        k_mma_qkv<<<gQKV, blk>>>(bstep,
                                 wq + (size_t)i * 128 * A_DIM,
                                 wk + (size_t)i * 128 * A_DIM,
                                 wv + (size_t)i * 128 * A_DIM,
                                 bq + i * A_DIM, bk + i * A_DIM, bv + i * A_DIM,
                                 bq2, bk2, bv2);
        k_flash_mma<<<gFl, fblk, FLASH_SMEM>>>(bq2, bk2, bv2, battn, inv_sqrt_d);
        k_mma_gemm<<<gF1, blk>>>(battn, w1 + (size_t)i * 128 * FFN_DIM,
                                 b1 + i * FFN_DIM, bh,
                                 A_DIM, A_DIM / 2, FFN_DIM, FFN_DIM, 1, 1);
        k_ffn2_ln<<<ROWS / 64, blk>>>(bh, w2 + (size_t)i * 512 * A_DIM,
                                      b2 + i * A_DIM, prev, step, bstep, lng, lnb);
    }

    // Conv1d(k=1) + ReLU -> bf16 entity encodings
    k_mma_gemm<<<gA, blk>>>(bstep, wc, bc, battn,
                            A_DIM, A_DIM / 2, A_DIM, A_DIM, 1, 1);
    // mean pool + final linear + ReLU
    k_pool_final<<<B_SZ, blk>>>(battn, We, be, out);
}

// round 10
// speedup vs baseline: 6.1907x; 1.0236x over previous
#include <cuda_runtime.h>
#include <math.h>

// Problem constants
#define B_SZ    16
#define N_SEQ   1024
#define H_HEADS 2
#define D_HEAD  128
#define A_DIM   256
#define FFN_DIM 1024
#define DEPTH   3
#define ROWS    (B_SZ * N_SEQ)   // 16384
#define LN_EPS  1e-5f

// ---------------- scratch (static device globals; no allocation) ------------
__device__ float g_step[ROWS * A_DIM];            // fp32 step (residual path)
__device__ __align__(16) unsigned gb_step[ROWS * A_DIM / 2];   // bf16 row-major
__device__ __align__(16) unsigned gb_q   [ROWS * A_DIM / 2];
__device__ __align__(16) unsigned gb_k   [ROWS * A_DIM / 2];
__device__ __align__(16) unsigned gb_v   [ROWS * A_DIM / 2];
__device__ __align__(16) unsigned gb_attn[ROWS * A_DIM / 2];
__device__ __align__(16) unsigned gb_h   [ROWS * FFN_DIM / 2];
// weights: plain bf16 [K][N] row-major (packed as unsigned[K][N/2])
__device__ __align__(16) unsigned gw_q[DEPTH * 128 * A_DIM];
__device__ __align__(16) unsigned gw_k[DEPTH * 128 * A_DIM];
__device__ __align__(16) unsigned gw_v[DEPTH * 128 * A_DIM];
__device__ __align__(16) unsigned gw_1[DEPTH * 128 * FFN_DIM];
__device__ __align__(16) unsigned gw_2[DEPTH * 512 * A_DIM];
__device__ __align__(16) unsigned gw_c[128 * A_DIM];

// ---------------- helpers ----------------------------------------------------
__device__ __forceinline__ unsigned packbf(float lo, float hi) {
    unsigned r;
    asm("cvt.rn.bf16x2.f32 %0, %1, %2;" : "=r"(r) : "f"(hi), "f"(lo));
    return r;
}
__device__ __forceinline__ unsigned prmtb(unsigned a, unsigned b, unsigned s) {
    unsigned r;
    asm("prmt.b32 %0,%1,%2,%3;" : "=r"(r) : "r"(a), "r"(b), "r"(s));
    return r;
}
__device__ __forceinline__ void mma_bf16(
    float& d0, float& d1, float& d2, float& d3,
    unsigned a0, unsigned a1, unsigned a2, unsigned a3,
    unsigned b0, unsigned b1)
{
    asm volatile(
        "mma.sync.aligned.m16n8k16.row.col.f32.bf16.bf16.f32 "
        "{%0,%1,%2,%3}, {%4,%5,%6,%7}, {%8,%9}, {%0,%1,%2,%3};"
        : "+f"(d0), "+f"(d1), "+f"(d2), "+f"(d3)
        : "r"(a0), "r"(a1), "r"(a2), "r"(a3), "r"(b0), "r"(b1));
}
__device__ __forceinline__ void ldsm4(unsigned& r0, unsigned& r1, unsigned& r2,
                                      unsigned& r3, unsigned addr)
{
    asm volatile("ldmatrix.sync.aligned.m8n8.x4.shared.b16 {%0,%1,%2,%3}, [%4];"
                 : "=r"(r0), "=r"(r1), "=r"(r2), "=r"(r3) : "r"(addr));
}
__device__ __forceinline__ void ldsm4t(unsigned& r0, unsigned& r1, unsigned& r2,
                                       unsigned& r3, unsigned addr)
{
    asm volatile("ldmatrix.sync.aligned.m8n8.x4.trans.shared.b16 {%0,%1,%2,%3}, [%4];"
                 : "=r"(r0), "=r"(r1), "=r"(r2), "=r"(r3) : "r"(addr));
}
__device__ __forceinline__ unsigned sptr(const void* p) {
    return (unsigned)__cvta_generic_to_shared(p);
}
#define CP16(dst, src) \
    asm volatile("cp.async.cg.shared.global [%0], [%1], 16;" :: "r"(dst), "l"(src))
#define CPCOMMIT() asm volatile("cp.async.commit_group;")
#define CPWAIT(n)  asm volatile("cp.async.wait_group %0;" :: "n"(n))

// ---------------- fused pack/convert kernel -----------------------------------
#define SEG_Q  98304
#define SEG_1  393216
#define SEG_2  393216
#define SEG_C  32768
#define PACK_TOTAL (3 * SEG_Q + SEG_1 + SEG_2 + SEG_C)       // 1114112
#define CVT_TOTAL  (ROWS * A_DIM / 4)                        // 1048576
__global__ void k_pack_all(
    const float* __restrict__ Wq, const float* __restrict__ Wk,
    const float* __restrict__ Wv, const float* __restrict__ W1,
    const float* __restrict__ W2, const float* __restrict__ Wc,
    const float* __restrict__ X,
    unsigned* __restrict__ wq, unsigned* __restrict__ wk, unsigned* __restrict__ wv,
    unsigned* __restrict__ w1, unsigned* __restrict__ w2, unsigned* __restrict__ wc,
    unsigned* __restrict__ bstep)
{
    int i = blockIdx.x * 256 + threadIdx.x;
    if (i < PACK_TOTAL) {
        const float* src; unsigned* dst; int N, j = i;
        if (j < 3 * SEG_Q) {
            int s = j / SEG_Q; j -= s * SEG_Q;
            src = (s == 0) ? Wq : (s == 1) ? Wk : Wv;
            dst = (s == 0) ? wq : (s == 1) ? wk : wv;
            N = A_DIM;
        } else if ((j -= 3 * SEG_Q) < SEG_1) {
            src = W1; dst = w1; N = FFN_DIM;
        } else if ((j -= SEG_1) < SEG_2) {
            src = W2; dst = w2; N = A_DIM;
        } else {
            j -= SEG_2; src = Wc; dst = wc; N = A_DIM;
        }
        // pairs along N: dst[gk][np] = (W[gk][2np], W[gk][2np+1])
        int half = N >> 1;
        int gk = j / half, np = j - gk * half;
        dst[j] = packbf(src[(size_t)gk * N + 2 * np],
                        src[(size_t)gk * N + 2 * np + 1]);
    } else {
        int j = i - PACK_TOTAL;
        if (j < CVT_TOTAL) {
            float4 v = *(const float4*)(X + (size_t)j * 4);
            bstep[2 * j]     = packbf(v.x, v.y);
            bstep[2 * j + 1] = packbf(v.z, v.w);
        }
    }
}

// ---------------- bf16 GEMM: 128x128 tile, BK=32, 8 warps, ldmatrix ---------
// A smem: [128 rows][PA=20] unsigned (k-pairs). B smem: [32 k][PBn=68] unsigned
// (n-pairs, unpacked k rows). 12 LDSM + 32 MMA per K-tile.
#define PA  20
#define PBn 68
#define A_STAGE (128 * PA)
#define B_STAGE (32 * PBn)

__device__ __forceinline__ void gemm_body(
    const unsigned* __restrict__ A2, const unsigned* __restrict__ Bp,
    const float* __restrict__ bias, void* Cout,
    int K, int lda2, int ldb2, int ldc, int mode, int relu, int m0, int n0)
{
    __shared__ unsigned As[2 * A_STAGE];
    __shared__ unsigned Bs[2 * B_STAGE];
    const int tid  = threadIdx.x;
    const int warp = tid >> 5;
    const int lane = tid & 31;
    const int grp  = lane >> 2;
    const int tig  = lane & 3;
    const int warpM = warp & 3;
    const int warpN = warp >> 2;
    const int nk = K >> 5;
    // ldmatrix per-thread address components
    const int aRow  = warpM * 32 + (lane & 15);
    const int aColU = (lane >> 4) * 4;
    const int bRow  = (lane & 7) + ((lane >> 3) & 1) * 8;
    const int bColU = warpN * 32 + (lane >> 4) * 4;

    {
        unsigned sa = sptr(As), sb = sptr(Bs);
#pragma unroll
        for (int it = 0; it < 2; it++) {
            int idx = tid + it * 256;
            int row = idx >> 2, c4 = (idx & 3) << 2;
            CP16(sa + (row * PA + c4) * 4, A2 + (size_t)(m0 + row) * lda2 + c4);
        }
#pragma unroll
        for (int it = 0; it < 2; it++) {
            int idx = tid + it * 256;
            int row = idx >> 4, c4 = (idx & 15) << 2;
            CP16(sb + (row * PBn + c4) * 4,
                 Bp + (size_t)row * ldb2 + (n0 >> 1) + c4);
        }
        CPCOMMIT();
    }

    float acc[2][8][4] = {};
    for (int i = 0; i < nk; i++) {
        if (i + 1 < nk) {
            int st = (i + 1) & 1;
            unsigned sa = sptr(As + st * A_STAGE), sb = sptr(Bs + st * B_STAGE);
            int kpn = (i + 1) * 16;      // k-pair offset (A)
            int kn  = (i + 1) * 32;      // k row offset (B)
#pragma unroll
            for (int it = 0; it < 2; it++) {
                int idx = tid + it * 256;
                int row = idx >> 2, c4 = (idx & 3) << 2;
                CP16(sa + (row * PA + c4) * 4,
                     A2 + (size_t)(m0 + row) * lda2 + kpn + c4);
            }
#pragma unroll
            for (int it = 0; it < 2; it++) {
                int idx = tid + it * 256;
                int row = idx >> 4, c4 = (idx & 15) << 2;
                CP16(sb + (row * PBn + c4) * 4,
                     Bp + (size_t)(kn + row) * ldb2 + (n0 >> 1) + c4);
            }
            CPCOMMIT();
            CPWAIT(1);
        } else {
            CPWAIT(0);
        }
        __syncthreads();

        const unsigned saB = sptr(As + (i & 1) * A_STAGE);
        const unsigned sbB = sptr(Bs + (i & 1) * B_STAGE);
#pragma unroll
        for (int kk = 0; kk < 2; kk++) {
            unsigned a0[4], a1[4];
            ldsm4(a0[0], a0[1], a0[2], a0[3],
                  saB + ((aRow)      * PA + aColU + kk * 8) * 4);
            ldsm4(a1[0], a1[1], a1[2], a1[3],
                  saB + ((aRow + 16) * PA + aColU + kk * 8) * 4);
#pragma unroll
            for (int np = 0; np < 4; np++) {
                unsigned b0, b1, b2, b3;
                ldsm4t(b0, b1, b2, b3,
                       sbB + ((kk * 16 + bRow) * PBn + bColU + np * 8) * 4);
                mma_bf16(acc[0][2*np][0], acc[0][2*np][1], acc[0][2*np][2], acc[0][2*np][3],
                         a0[0], a0[1], a0[2], a0[3], b0, b1);
                mma_bf16(acc[0][2*np+1][0], acc[0][2*np+1][1], acc[0][2*np+1][2], acc[0][2*np+1][3],
                         a0[0], a0[1], a0[2], a0[3], b2, b3);
                mma_bf16(acc[1][2*np][0], acc[1][2*np][1], acc[1][2*np][2], acc[1][2*np][3],
                         a1[0], a1[1], a1[2], a1[3], b0, b1);
                mma_bf16(acc[1][2*np+1][0], acc[1][2*np+1][1], acc[1][2*np+1][2], acc[1][2*np+1][3],
                         a1[0], a1[1], a1[2], a1[3], b2, b3);
            }
        }
        __syncthreads();
    }

#pragma unroll
    for (int mf = 0; mf < 2; mf++) {
        const int row = m0 + warpM * 32 + mf * 16 + grp;
#pragma unroll
        for (int nf = 0; nf < 8; nf++) {
            const int col = n0 + warpN * 64 + nf * 8 + 2 * tig;
            float bx = 0.f, by = 0.f;
            if (bias) { float2 bb = *(const float2*)(bias + col); bx = bb.x; by = bb.y; }
            float v0 = acc[mf][nf][0] + bx, v1 = acc[mf][nf][1] + by;
            float v2 = acc[mf][nf][2] + bx, v3 = acc[mf][nf][3] + by;
            if (relu) {
                v0 = fmaxf(v0, 0.f); v1 = fmaxf(v1, 0.f);
                v2 = fmaxf(v2, 0.f); v3 = fmaxf(v3, 0.f);
            }
            if (mode == 0) {
                float* C = (float*)Cout;
                *(float2*)(C + (size_t)row * ldc + col)       = make_float2(v0, v1);
                *(float2*)(C + (size_t)(row + 8) * ldc + col) = make_float2(v2, v3);
            } else {
                unsigned* C2 = (unsigned*)Cout;
                const int ldc2 = ldc >> 1;
                C2[(size_t)row * ldc2 + (col >> 1)]       = packbf(v0, v1);
                C2[(size_t)(row + 8) * ldc2 + (col >> 1)] = packbf(v2, v3);
            }
        }
    }
}

__global__ void __launch_bounds__(256) k_mma_gemm(
    const unsigned* __restrict__ A2, const unsigned* __restrict__ Bp,
    const float* __restrict__ bias, void* Cout,
    int K, int lda2, int ldb2, int ldc, int mode, int relu)
{
    gemm_body(A2, Bp, bias, Cout, K, lda2, ldb2, ldc, mode, relu,
              blockIdx.y * 128, blockIdx.x * 128);
}

__global__ void __launch_bounds__(256) k_mma_qkv(
    const unsigned* __restrict__ A2,
    const unsigned* __restrict__ W0, const unsigned* __restrict__ W1p,
    const unsigned* __restrict__ W2p,
    const float* __restrict__ c0, const float* __restrict__ c1,
    const float* __restrict__ c2,
    unsigned* __restrict__ O0, unsigned* __restrict__ O1, unsigned* __restrict__ O2)
{
    const unsigned* W; const float* bb; unsigned* O;
    if (blockIdx.z == 0)      { W = W0;  bb = c0; O = O0; }
    else if (blockIdx.z == 1) { W = W1p; bb = c1; O = O1; }
    else                      { W = W2p; bb = c2; O = O2; }
    gemm_body(A2, W, bb, O, A_DIM, A_DIM / 2, A_DIM / 2, A_DIM, 1, 0,
              blockIdx.y * 128, blockIdx.x * 128);
}

// ---------------- fused FFN2 + bias + relu + residual + LayerNorm ------------
// Tile 64 rows x 256 cols. 8 warps: warpM(2) x warpN(4). ldmatrix fragments.
#define F2PA  20
#define F2PBn 132
#define F2_AS (64 * F2PA)
#define F2_BS (32 * F2PBn)

__global__ void __launch_bounds__(256, 2) k_ffn2_ln(
    const unsigned* __restrict__ A2,      // bh [ROWS][512]
    const unsigned* __restrict__ Bp,      // w2 layer bf16 [1024][256] -> u[1024][128]
    const float* __restrict__ bias,
    const float* __restrict__ prev,
    float* __restrict__ step, unsigned* __restrict__ step2,
    const float* __restrict__ g, const float* __restrict__ b)
{
    __shared__ unsigned As[2 * F2_AS];
    __shared__ unsigned Bs[2 * F2_BS];
    __shared__ float reds[4][64], redq[4][64];
    const int tid  = threadIdx.x;
    const int warp = tid >> 5;
    const int lane = tid & 31;
    const int grp  = lane >> 2;
    const int tig  = lane & 3;
    const int warpM = warp & 1;
    const int warpN = warp >> 1;
    const int m0 = blockIdx.x * 64;
    const int nk = FFN_DIM / 32;          // 32
    const int aRow  = warpM * 32 + (lane & 15);
    const int aColU = (lane >> 4) * 4;
    const int bRow  = (lane & 7) + ((lane >> 3) & 1) * 8;
    const int bColU = warpN * 32 + (lane >> 4) * 4;

    {
        unsigned sa = sptr(As), sb = sptr(Bs);
        {   // A: 64 rows x 16 pairs = 256 uint4
            int row = tid >> 2, c4 = (tid & 3) << 2;
            CP16(sa + (row * F2PA + c4) * 4, A2 + (size_t)(m0 + row) * 512 + c4);
        }
#pragma unroll
        for (int it = 0; it < 4; it++) {  // B: 32 k x 128 u = 1024 uint4
            int idx = tid + it * 256;
            int row = idx >> 5, c4 = (idx & 31) << 2;
            CP16(sb + (row * F2PBn + c4) * 4, Bp + (size_t)row * 128 + c4);
        }
        CPCOMMIT();
    }

    float acc[2][8][4] = {};
    for (int i = 0; i < nk; i++) {
        if (i + 1 < nk) {
            int st = (i + 1) & 1;
            unsigned sa = sptr(As + st * F2_AS), sb = sptr(Bs + st * F2_BS);
            int kpn = (i + 1) * 16;
            int kn  = (i + 1) * 32;
            {
                int row = tid >> 2, c4 = (tid & 3) << 2;
                CP16(sa + (row * F2PA + c4) * 4,
                     A2 + (size_t)(m0 + row) * 512 + kpn + c4);
            }
#pragma unroll
            for (int it = 0; it < 4; it++) {
                int idx = tid + it * 256;
                int row = idx >> 5, c4 = (idx & 31) << 2;
                CP16(sb + (row * F2PBn + c4) * 4,
                     Bp + (size_t)(kn + row) * 128 + c4);
            }
            CPCOMMIT();
            CPWAIT(1);
        } else {
            CPWAIT(0);
        }
        __syncthreads();

        const unsigned saB = sptr(As + (i & 1) * F2_AS);
        const unsigned sbB = sptr(Bs + (i & 1) * F2_BS);
#pragma unroll
        for (int kk = 0; kk < 2; kk++) {
            unsigned a0[4], a1[4];
            ldsm4(a0[0], a0[1], a0[2], a0[3],
                  saB + ((aRow)      * F2PA + aColU + kk * 8) * 4);
            ldsm4(a1[0], a1[1], a1[2], a1[3],
                  saB + ((aRow + 16) * F2PA + aColU + kk * 8) * 4);
#pragma unroll
            for (int np = 0; np < 4; np++) {
                unsigned b0, b1, b2, b3;
                ldsm4t(b0, b1, b2, b3,
                       sbB + ((kk * 16 + bRow) * F2PBn + bColU + np * 8) * 4);
                mma_bf16(acc[0][2*np][0], acc[0][2*np][1], acc[0][2*np][2], acc[0][2*np][3],
                         a0[0], a0[1], a0[2], a0[3], b0, b1);
                mma_bf16(acc[0][2*np+1][0], acc[0][2*np+1][1], acc[0][2*np+1][2], acc[0][2*np+1][3],
                         a0[0], a0[1], a0[2], a0[3], b2, b3);
                mma_bf16(acc[1][2*np][0], acc[1][2*np][1], acc[1][2*np][2], acc[1][2*np][3],
                         a1[0], a1[1], a1[2], a1[3], b0, b1);
                mma_bf16(acc[1][2*np+1][0], acc[1][2*np+1][1], acc[1][2*np+1][2], acc[1][2*np+1][3],
                         a1[0], a1[1], a1[2], a1[3], b2, b3);
            }
        }
        __syncthreads();
    }

    // ---- epilogue: bias + relu + residual, partial LN stats ----
#pragma unroll
    for (int mf = 0; mf < 2; mf++) {
#pragma unroll
        for (int half = 0; half < 2; half++) {
            const int rloc = warpM * 32 + mf * 16 + half * 8 + grp;
            const int row  = m0 + rloc;
            const int ai   = half * 2;
            float sum = 0.f, sq = 0.f;
#pragma unroll
            for (int nf = 0; nf < 8; nf++) {
                const int col = warpN * 64 + nf * 8 + 2 * tig;
                float2 bb = *(const float2*)(bias + col);
                float2 pv = *(const float2*)(prev + (size_t)row * A_DIM + col);
                float v0 = fmaxf(acc[mf][nf][ai]     + bb.x, 0.f) + pv.x;
                float v1 = fmaxf(acc[mf][nf][ai + 1] + bb.y, 0.f) + pv.y;
                acc[mf][nf][ai] = v0; acc[mf][nf][ai + 1] = v1;
                sum += v0 + v1;
                sq  += v0 * v0 + v1 * v1;
            }
            sum += __shfl_xor_sync(0xffffffffu, sum, 1);
            sum += __shfl_xor_sync(0xffffffffu, sum, 2);
            sq  += __shfl_xor_sync(0xffffffffu, sq, 1);
            sq  += __shfl_xor_sync(0xffffffffu, sq, 2);
            if (tig == 0) { reds[warpN][rloc] = sum; redq[warpN][rloc] = sq; }
        }
    }
    __syncthreads();

    // ---- finish LN and write fp32 + bf16 ----
#pragma unroll
    for (int mf = 0; mf < 2; mf++) {
#pragma unroll
        for (int half = 0; half < 2; half++) {
            const int rloc = warpM * 32 + mf * 16 + half * 8 + grp;
            const int row  = m0 + rloc;
            const int ai   = half * 2;
            float s = reds[0][rloc] + reds[1][rloc] + reds[2][rloc] + reds[3][rloc];
            float q = redq[0][rloc] + redq[1][rloc] + redq[2][rloc] + redq[3][rloc];
            float mu  = s * (1.f / A_DIM);
            float var = q * (1.f / A_DIM) - mu * mu;
            float rs  = rsqrtf(var + LN_EPS);
#pragma unroll
            for (int nf = 0; nf < 8; nf++) {
                const int col = warpN * 64 + nf * 8 + 2 * tig;
                float2 gg = *(const float2*)(g + col);
                float2 b2v = *(const float2*)(b + col);
                float y0 = (acc[mf][nf][ai]     - mu) * rs * gg.x + b2v.x;
                float y1 = (acc[mf][nf][ai + 1] - mu) * rs * gg.y + b2v.y;
                *(float2*)(step + (size_t)row * A_DIM + col) = make_float2(y0, y1);
                step2[(size_t)row * (A_DIM / 2) + (col >> 1)] = packbf(y0, y1);
            }
        }
    }
}

// ---------------- flash attention (unchanged from R9) ------------------------
#define FQT 64
#define FKT 64
#define PQ  68
#define PV  136
#define PPS 36
#define FLASH_SMEM ((64 * PQ + 64 * PQ + 32 * PV + 64 * PPS) * 4)  // 61440 B

__global__ void __launch_bounds__(128, 2) k_flash_mma(
    const unsigned* __restrict__ Q2, const unsigned* __restrict__ K2,
    const unsigned* __restrict__ V2, unsigned* __restrict__ Out2, float alpha)
{
    const int bh = blockIdx.y;
    const size_t base2 = (size_t)(bh >> 1) * N_SEQ * 128 + (size_t)(bh & 1) * 64;
    const int q0   = blockIdx.x * FQT;
    const int tid  = threadIdx.x;
    const int warp = tid >> 5;
    const int lane = tid & 31;
    const int grp  = lane >> 2;
    const int tig  = lane & 3;
    const int rb   = warp * 16;

    extern __shared__ unsigned fsm[];
    unsigned* Qs = fsm;
    unsigned* Ks = fsm + 64 * PQ;
    unsigned* Vs = fsm + 128 * PQ;
    unsigned* Ps = Vs + 32 * PV;

    {
        unsigned sq = sptr(Qs), sk = sptr(Ks);
#pragma unroll
        for (int it = 0; it < 8; it++) {
            int idx = tid + it * 128;
            int row = idx >> 4, c4 = (idx & 15) << 2;
            CP16(sq + (row * PQ + c4) * 4, Q2 + base2 + (size_t)(q0 + row) * 128 + c4);
            CP16(sk + (row * PQ + c4) * 4, K2 + base2 + (size_t)row * 128 + c4);
        }
        CPCOMMIT();
        CPWAIT(0);
    }
    __syncthreads();

    float o[16][4] = {};
    float mr0 = -1e30f, mr1 = -1e30f, l0 = 0.f, l1 = 0.f;

    for (int t = 0; t < N_SEQ / FKT; t++) {
        const int k0 = t * FKT;

        uint4 va[4], vb[4];
#pragma unroll
        for (int it = 0; it < 4; it++) {
            int idx = tid + it * 128;
            int kp = idx >> 4, dpq = idx & 15;
            const unsigned* r0 = V2 + base2 + (size_t)(k0 + 2 * kp) * 128 + dpq * 4;
            va[it] = *(const uint4*)r0;
            vb[it] = *(const uint4*)(r0 + 128);
        }

        float s[8][4] = {};
#pragma unroll
        for (int kk = 0; kk < 8; kk++) {
            const int kc2 = kk * 8;
            unsigned a0 = Qs[(rb + grp)     * PQ + kc2 + tig];
            unsigned a1 = Qs[(rb + grp + 8) * PQ + kc2 + tig];
            unsigned a2 = Qs[(rb + grp)     * PQ + kc2 + tig + 4];
            unsigned a3 = Qs[(rb + grp + 8) * PQ + kc2 + tig + 4];
#pragma unroll
            for (int nf = 0; nf < 8; nf++) {
                const int key = nf * 8 + grp;
                unsigned b0 = Ks[key * PQ + kc2 + tig];
                unsigned b1 = Ks[key * PQ + kc2 + tig + 4];
                mma_bf16(s[nf][0], s[nf][1], s[nf][2], s[nf][3],
                         a0, a1, a2, a3, b0, b1);
            }
        }

#pragma unroll
        for (int it = 0; it < 4; it++) {
            int idx = tid + it * 128;
            int kp = idx >> 4, dpq = idx & 15;
            uint4 a = va[it], bbv = vb[it];
            uint4 w0, w1;
            w0.x = prmtb(a.x, bbv.x, 0x5410u); w0.y = prmtb(a.x, bbv.x, 0x7632u);
            w0.z = prmtb(a.y, bbv.y, 0x5410u); w0.w = prmtb(a.y, bbv.y, 0x7632u);
            w1.x = prmtb(a.z, bbv.z, 0x5410u); w1.y = prmtb(a.z, bbv.z, 0x7632u);
            w1.z = prmtb(a.w, bbv.w, 0x5410u); w1.w = prmtb(a.w, bbv.w, 0x7632u);
            *(uint4*)&Vs[kp * PV + 8 * dpq]     = w0;
            *(uint4*)&Vs[kp * PV + 8 * dpq + 4] = w1;
        }

#pragma unroll
        for (int nf = 0; nf < 8; nf++) {
            s[nf][0] *= alpha; s[nf][1] *= alpha;
            s[nf][2] *= alpha; s[nf][3] *= alpha;
        }
        float rmax0 = -1e30f, rmax1 = -1e30f;
#pragma unroll
        for (int nf = 0; nf < 8; nf++) {
            rmax0 = fmaxf(rmax0, fmaxf(s[nf][0], s[nf][1]));
            rmax1 = fmaxf(rmax1, fmaxf(s[nf][2], s[nf][3]));
        }
#pragma unroll
        for (int w = 1; w < 4; w <<= 1) {
            rmax0 = fmaxf(rmax0, __shfl_xor_sync(0xffffffffu, rmax0, w));
            rmax1 = fmaxf(rmax1, __shfl_xor_sync(0xffffffffu, rmax1, w));
        }
        float mn0 = fmaxf(mr0, rmax0), mn1 = fmaxf(mr1, rmax1);
        float sc0 = __expf(mr0 - mn0), sc1 = __expf(mr1 - mn1);
        mr0 = mn0; mr1 = mn1;
        l0 *= sc0; l1 *= sc1;
#pragma unroll
        for (int nf = 0; nf < 16; nf++) {
            o[nf][0] *= sc0; o[nf][1] *= sc0;
            o[nf][2] *= sc1; o[nf][3] *= sc1;
        }
        float rs0 = 0.f, rs1 = 0.f;
#pragma unroll
        for (int nf = 0; nf < 8; nf++) {
            float p0 = __expf(s[nf][0] - mn0);
            float p1 = __expf(s[nf][1] - mn0);
            float p2 = __expf(s[nf][2] - mn1);
            float p3 = __expf(s[nf][3] - mn1);
            rs0 += p0 + p1; rs1 += p2 + p3;
            const int kp = nf * 4 + tig;
            Ps[(rb + grp)     * PPS + kp] = packbf(p0, p1);
            Ps[(rb + grp + 8) * PPS + kp] = packbf(p2, p3);
        }
#pragma unroll
        for (int w = 1; w < 4; w <<= 1) {
            rs0 += __shfl_xor_sync(0xffffffffu, rs0, w);
            rs1 += __shfl_xor_sync(0xffffffffu, rs1, w);
        }
        l0 += rs0; l1 += rs1;

        __syncthreads();

        if (t + 1 < N_SEQ / FKT) {
            unsigned sk = sptr(Ks);
#pragma unroll
            for (int it = 0; it < 8; it++) {
                int idx = tid + it * 128;
                int row = idx >> 4, c4 = (idx & 15) << 2;
                CP16(sk + (row * PQ + c4) * 4,
                     K2 + base2 + (size_t)(k0 + FKT + row) * 128 + c4);
            }
            CPCOMMIT();
        }

#pragma unroll
        for (int kk = 0; kk < 4; kk++) {
            const int kc2 = kk * 8;
            unsigned a0 = Ps[(rb + grp)     * PPS + kc2 + tig];
            unsigned a1 = Ps[(rb + grp + 8) * PPS + kc2 + tig];
            unsigned a2 = Ps[(rb + grp)     * PPS + kc2 + tig + 4];
            unsigned a3 = Ps[(rb + grp + 8) * PPS + kc2 + tig + 4];
#pragma unroll
            for (int nf = 0; nf < 16; nf++) {
                const int col = nf * 8 + grp;
                unsigned b0 = Vs[(kc2 + tig)     * PV + col];
                unsigned b1 = Vs[(kc2 + tig + 4) * PV + col];
                mma_bf16(o[nf][0], o[nf][1], o[nf][2], o[nf][3],
                         a0, a1, a2, a3, b0, b1);
            }
        }

        if (t + 1 < N_SEQ / FKT) { CPWAIT(0); }
        __syncthreads();
    }

    const float inv0 = 1.f / l0, inv1 = 1.f / l1;
    const int row0 = q0 + rb + grp;
#pragma unroll
    for (int nf = 0; nf < 16; nf++) {
        const int c2 = nf * 4 + tig;
        Out2[base2 + (size_t)row0 * 128 + c2] =
            packbf(o[nf][0] * inv0, o[nf][1] * inv0);
        Out2[base2 + (size_t)(row0 + 8) * 128 + c2] =
            packbf(o[nf][2] * inv1, o[nf][3] * inv1);
    }
}

// ---------------- pool + final linear (reads bf16 E) -------------------------
__global__ void k_pool_final(const unsigned* __restrict__ E2,
                             const float* __restrict__ We,
                             const float* __restrict__ be, float* __restrict__ out)
{
    const int b = blockIdx.x;
    const int t = threadIdx.x;
    __shared__ float pr[A_DIM];
    const unsigned* base = E2 + (size_t)b * N_SEQ * 128 + (t >> 1);
    const int hi = t & 1;
    float s0 = 0.f, s1 = 0.f, s2 = 0.f, s3 = 0.f;
    for (int n = 0; n < N_SEQ; n += 4) {
        unsigned w0 = base[(size_t)(n + 0) * 128];
        unsigned w1 = base[(size_t)(n + 1) * 128];
        unsigned w2 = base[(size_t)(n + 2) * 128];
        unsigned w3 = base[(size_t)(n + 3) * 128];
        s0 += __uint_as_float(hi ? (w0 & 0xffff0000u) : (w0 << 16));
        s1 += __uint_as_float(hi ? (w1 & 0xffff0000u) : (w1 << 16));
        s2 += __uint_as_float(hi ? (w2 & 0xffff0000u) : (w2 << 16));
        s3 += __uint_as_float(hi ? (w3 & 0xffff0000u) : (w3 << 16));
    }
    pr[t] = (s0 + s1 + s2 + s3) * (1.f / N_SEQ);
    __syncthreads();
    float acc = 0.f;
#pragma unroll 8
    for (int k = 0; k < A_DIM; k++) acc = fmaf(pr[k], We[k * A_DIM + t], acc);
    out[b * A_DIM + t] = fmaxf(acc + be[t], 0.f);
}

// ---------------- launcher ---------------------------------------------------
extern "C" void kernel_launch(void* const* d_in, const int* in_sizes, int n_in,
                              void* d_out, int out_size)
{
    const float* X   = (const float*)d_in[0];
    const float* Wq  = (const float*)d_in[1];
    const float* bq  = (const float*)d_in[2];
    const float* Wk  = (const float*)d_in[3];
    const float* bk  = (const float*)d_in[4];
    const float* Wv  = (const float*)d_in[5];
    const float* bv  = (const float*)d_in[6];
    const float* W1  = (const float*)d_in[7];
    const float* b1  = (const float*)d_in[8];
    const float* W2  = (const float*)d_in[9];
    const float* b2  = (const float*)d_in[10];
    const float* lng = (const float*)d_in[11];
    const float* lnb = (const float*)d_in[12];
    const float* Wc  = (const float*)d_in[13];
    const float* bc  = (const float*)d_in[14];
    const float* We  = (const float*)d_in[15];
    const float* be  = (const float*)d_in[16];
    float* out = (float*)d_out;

    static float *step = nullptr;
    static unsigned *bstep, *bq2, *bk2, *bv2, *battn, *bh;
    static unsigned *wq, *wk, *wv, *w1, *w2, *wc;
    if (!step) {
        cudaGetSymbolAddress((void**)&step,  g_step);
        cudaGetSymbolAddress((void**)&bstep, gb_step);
        cudaGetSymbolAddress((void**)&bq2,   gb_q);
        cudaGetSymbolAddress((void**)&bk2,   gb_k);
        cudaGetSymbolAddress((void**)&bv2,   gb_v);
        cudaGetSymbolAddress((void**)&battn, gb_attn);
        cudaGetSymbolAddress((void**)&bh,    gb_h);
        cudaGetSymbolAddress((void**)&wq,    gw_q);
        cudaGetSymbolAddress((void**)&wk,    gw_k);
        cudaGetSymbolAddress((void**)&wv,    gw_v);
        cudaGetSymbolAddress((void**)&w1,    gw_1);
        cudaGetSymbolAddress((void**)&w2,    gw_2);
        cudaGetSymbolAddress((void**)&wc,    gw_c);
        cudaFuncSetAttribute(k_flash_mma,
                             cudaFuncAttributeMaxDynamicSharedMemorySize, FLASH_SMEM);
    }

    {
        int total = PACK_TOTAL + CVT_TOTAL;
        k_pack_all<<<(total + 255) / 256, 256>>>(Wq, Wk, Wv, W1, W2, Wc, X,
                                                 wq, wk, wv, w1, w2, wc, bstep);
    }

    const dim3 blk(256);
    const dim3 fblk(128);
    const dim3 gQKV(2, ROWS / 128, 3);
    const dim3 gF1 (8, ROWS / 128);
    const dim3 gA  (2, ROWS / 128);
    const dim3 gFl (N_SEQ / FQT, B_SZ * H_HEADS);
    const float inv_sqrt_d = 0.08838834764831845f;

    for (int i = 0; i < DEPTH; i++) {
        const float* prev = (i == 0) ? X : step;
        k_mma_qkv<<<gQKV, blk>>>(bstep,
                                 wq + (size_t)i * 128 * A_DIM,
                                 wk + (size_t)i * 128 * A_DIM,
                                 wv + (size_t)i * 128 * A_DIM,
                                 bq + i * A_DIM, bk + i * A_DIM, bv + i * A_DIM,
                                 bq2, bk2, bv2);
        k_flash_mma<<<gFl, fblk, FLASH_SMEM>>>(bq2, bk2, bv2, battn, inv_sqrt_d);
        k_mma_gemm<<<gF1, blk>>>(battn, w1 + (size_t)i * 128 * FFN_DIM,
                                 b1 + i * FFN_DIM, bh,
                                 A_DIM, A_DIM / 2, FFN_DIM / 2, FFN_DIM, 1, 1);
        k_ffn2_ln<<<ROWS / 64, blk>>>(bh, w2 + (size_t)i * 512 * A_DIM,
                                      b2 + i * A_DIM, prev, step, bstep, lng, lnb);
    }

    // Conv1d(k=1) + ReLU -> bf16 entity encodings
    k_mma_gemm<<<gA, blk>>>(bstep, wc, bc, battn,
                            A_DIM, A_DIM / 2, A_DIM / 2, A_DIM, 1, 1);
    // mean pool + final linear + ReLU
    k_pool_final<<<B_SZ, blk>>>(battn, We, be, out);
}